// round 1
// baseline (speedup 1.0000x reference)
#include <cuda_runtime.h>
#include <math.h>

// Problem constants
#define BB 2
#define SS 1024
#define DD 1024
#define HH 16
#define LL 4
#define DHH 64
#define MR 2048  // B*S

// Scratch (device globals; no allocation)
__device__ float g_x [MR * DD];
__device__ float g_qh[MR * DD];
__device__ float g_vh[MR * DD];
__device__ float g_ao[MR * DD];
__device__ float g_y [MR * DD];
__device__ float g_sc[(size_t)BB * HH * SS * SS];  // 128 MB

// ---------------------------------------------------------------------------
// Block reduction helpers (blockDim.x == 256 -> 8 warps)
// ---------------------------------------------------------------------------
__device__ __forceinline__ float blkMax(float v, float* red) {
    int lane = threadIdx.x & 31, w = threadIdx.x >> 5;
#pragma unroll
    for (int o = 16; o; o >>= 1) v = fmaxf(v, __shfl_xor_sync(0xffffffffu, v, o));
    if (lane == 0) red[w] = v;
    __syncthreads();
    float r = red[0];
#pragma unroll
    for (int i = 1; i < 8; i++) r = fmaxf(r, red[i]);
    __syncthreads();
    return r;
}

__device__ __forceinline__ float blkSum(float v, float* red) {
    int lane = threadIdx.x & 31, w = threadIdx.x >> 5;
#pragma unroll
    for (int o = 16; o; o >>= 1) v += __shfl_xor_sync(0xffffffffu, v, o);
    if (lane == 0) red[w] = v;
    __syncthreads();
    float r = 0.f;
#pragma unroll
    for (int i = 0; i < 8; i++) r += red[i];
    __syncthreads();
    return r;
}

// ---------------------------------------------------------------------------
// Copy input q -> g_x
// ---------------------------------------------------------------------------
__global__ void copy_in(const float* __restrict__ src) {
    int i = blockIdx.x * blockDim.x + threadIdx.x;
    g_x[i] = src[i];
}

// ---------------------------------------------------------------------------
// SGEMM + bias: C[2048,1024] = A[2048,1024] @ W[1024,1024] + bias
// mode: 0 -> A=g_x, C=g_qh ; 1 -> A=g_x, C=g_vh ; 2 -> A=g_ao, C=g_y
// 128x128 tile, BK=16, 256 threads, 8x8 micro-tile.
// ---------------------------------------------------------------------------
__global__ __launch_bounds__(256) void sgemm_bias(int mode,
                                                  const float* __restrict__ W,
                                                  const float* __restrict__ bias) {
    const float* A = (mode == 2) ? g_ao : g_x;
    float* C = (mode == 0) ? g_qh : (mode == 1) ? g_vh : g_y;

    const int m0 = blockIdx.y * 128, n0 = blockIdx.x * 128;
    __shared__ float As[128][17];
    __shared__ float Bs[16][128];

    const int tid = threadIdx.x, tx = tid & 15, ty = tid >> 4;
    float acc[8][8] = {};

    for (int k0 = 0; k0 < 1024; k0 += 16) {
#pragma unroll
        for (int i = 0; i < 8; i++) {
            int idx = tid + i * 256;
            int r = idx >> 4, c = idx & 15;
            As[r][c] = A[(size_t)(m0 + r) * 1024 + k0 + c];
        }
#pragma unroll
        for (int i = 0; i < 8; i++) {
            int idx = tid + i * 256;
            int r = idx >> 7, c = idx & 127;
            Bs[r][c] = W[(size_t)(k0 + r) * 1024 + n0 + c];
        }
        __syncthreads();
#pragma unroll
        for (int kk = 0; kk < 16; kk++) {
            float a[8], b[8];
#pragma unroll
            for (int i = 0; i < 8; i++) a[i] = As[ty * 8 + i][kk];
#pragma unroll
            for (int j = 0; j < 8; j++) b[j] = Bs[kk][tx * 8 + j];
#pragma unroll
            for (int i = 0; i < 8; i++)
#pragma unroll
                for (int j = 0; j < 8; j++) acc[i][j] += a[i] * b[j];
        }
        __syncthreads();
    }

#pragma unroll
    for (int i = 0; i < 8; i++) {
        int row = m0 + ty * 8 + i;
#pragma unroll
        for (int j = 0; j < 8; j++) {
            int col = n0 + tx * 8 + j;
            C[(size_t)row * 1024 + col] = acc[i][j] + bias[col];
        }
    }
}

// ---------------------------------------------------------------------------
// Scores: for each (b,h): S = Qh @ Qh^T / 8. 64x64 tiles; skip tiles strictly
// above the diagonal (never read by the causal attention kernel).
// ---------------------------------------------------------------------------
__global__ __launch_bounds__(256) void scores_kernel() {
    const int kt = blockIdx.x, qt = blockIdx.y, bh = blockIdx.z;
    if (kt > qt) return;
    const int b = bh >> 4, h = bh & 15;
    const int q0 = qt * 64, k0 = kt * 64;

    __shared__ float Qs[64][65];
    __shared__ float Ks[64][65];

    const int tid = threadIdx.x, tx = tid & 15, ty = tid >> 4;
    const float* qbase = g_qh + (size_t)(b * SS) * DD + h * DHH;

#pragma unroll
    for (int i = 0; i < 16; i++) {
        int idx = tid + i * 256;
        int r = idx >> 6, c = idx & 63;
        Qs[r][c] = qbase[(size_t)(q0 + r) * DD + c];
        Ks[r][c] = qbase[(size_t)(k0 + r) * DD + c];
    }
    __syncthreads();

    float acc[4][4] = {};
#pragma unroll 8
    for (int kk = 0; kk < 64; kk++) {
        float a[4], b2[4];
#pragma unroll
        for (int i = 0; i < 4; i++) a[i] = Qs[ty * 4 + i][kk];
#pragma unroll
        for (int j = 0; j < 4; j++) b2[j] = Ks[tx * 4 + j][kk];
#pragma unroll
        for (int i = 0; i < 4; i++)
#pragma unroll
            for (int j = 0; j < 4; j++) acc[i][j] += a[i] * b2[j];
    }

#pragma unroll
    for (int i = 0; i < 4; i++) {
        size_t rowoff = ((size_t)bh * SS + q0 + ty * 4 + i) * SS + k0;
#pragma unroll
        for (int j = 0; j < 4; j++)
            g_sc[rowoff + tx * 4 + j] = acc[i][j] * 0.125f;
    }
}

// ---------------------------------------------------------------------------
// Attention row kernel: one block per (b,h,q). 256 threads, 4 keys/thread.
// softmax -> cumsum scan -> distance decay -> softmax -> maxout -> PV
// ---------------------------------------------------------------------------
__global__ __launch_bounds__(256) void attn_kernel(const float* __restrict__ gam) {
    const int q = blockIdx.x, h = blockIdx.y, b = blockIdx.z;
    const int bh = b * HH + h;
    const int tid = threadIdx.x, lane = tid & 31, w = tid >> 5;

    float* aorow = g_ao + (size_t)(b * SS + q) * DD + h * DHH;
    const int nv = q;  // strict causal: keys 0..q-1
    if (nv == 0) {
        if (tid < 64) aorow[tid] = 0.f;
        return;
    }

    __shared__ float s_c[1024];
    __shared__ float red[8];
    __shared__ float pred[8][64];

    const float* srow = g_sc + ((size_t)bh * SS + q) * SS;
    const float gneg = -fabsf(gam[h]);
    const int k0 = tid * 4;

    float sv[4];
    bool val[4];
    float m1 = -3.0e38f;
#pragma unroll
    for (int i = 0; i < 4; i++) {
        int k = k0 + i;
        val[i] = (k < nv);
        sv[i] = val[i] ? srow[k] : 0.f;
        if (val[i]) m1 = fmaxf(m1, sv[i]);
    }
    m1 = blkMax(m1, red);

    float e[4];
#pragma unroll
    for (int i = 0; i < 4; i++) e[i] = val[i] ? expf(sv[i] - m1) : 0.f;

    // inclusive block scan over 1024 contiguous values (4 per thread)
    float l0 = e[0], l1 = l0 + e[1], l2 = l1 + e[2], l3 = l2 + e[3];
    float tot = l3, xs = tot;
#pragma unroll
    for (int o = 1; o < 32; o <<= 1) {
        float y = __shfl_up_sync(0xffffffffu, xs, o);
        if (lane >= o) xs += y;
    }
    if (lane == 31) red[w] = xs;
    __syncthreads();
    float woff = 0.f, sum1 = 0.f;
#pragma unroll
    for (int i = 0; i < 8; i++) {
        float t = red[i];
        sum1 += t;
        if (i < w) woff += t;
    }
    __syncthreads();
    const float exc = woff + xs - tot;
    float cum[4] = {exc + l0, exc + l1, exc + l2, exc + l3};

    const float rs = 1.f / sum1;
    float s2[4];
    float m2 = -3.0e38f;
#pragma unroll
    for (int i = 0; i < 4; i++) {
        if (val[i]) {
            float frac = fmaxf((sum1 - cum[i]) * rs, 0.f);
            float dist = sqrtf(frac * (float)(q - (k0 + i)));
            float eff = expf(dist * gneg);
            eff = fminf(fmaxf(eff, 1e-5f), 1e5f);
            s2[i] = sv[i] * eff;
            m2 = fmaxf(m2, s2[i]);
        } else {
            s2[i] = 0.f;
        }
    }
    m2 = blkMax(m2, red);

    float a[4], lsum = 0.f, lmax = 0.f;
#pragma unroll
    for (int i = 0; i < 4; i++) {
        a[i] = val[i] ? expf(s2[i] - m2) : 0.f;
        lsum += a[i];
        lmax = fmaxf(lmax, a[i]);
    }
    float sum2 = blkSum(lsum, red);
    float amax = blkMax(lmax, red);
    // scale = min(1/max(attn), 5); attn = a/sum2 -> coeff = a * min(sum2/amax,5)/sum2
    const float coef = fminf(sum2 / amax, 5.f) / sum2;
#pragma unroll
    for (int i = 0; i < 4; i++) s_c[k0 + i] = a[i] * coef;
    __syncthreads();

    // PV: each warp covers 128 keys; lane accumulates d=lane and d=lane+32
    float acc0 = 0.f, acc1 = 0.f;
    const int kb = w * 128;
    const int ke = min(kb + 128, nv);
    const float* vb = g_vh + (size_t)(b * SS) * DD + h * DHH + lane;
#pragma unroll 4
    for (int k = kb; k < ke; k++) {
        float c = s_c[k];
        const float* vr = vb + (size_t)k * DD;
        acc0 += c * vr[0];
        acc1 += c * vr[32];
    }
    pred[w][lane] = acc0;
    pred[w][lane + 32] = acc1;
    __syncthreads();
    if (tid < 64) {
        float s = 0.f;
#pragma unroll
        for (int i = 0; i < 8; i++) s += pred[i][tid];
        aorow[tid] = s;
    }
}

// ---------------------------------------------------------------------------
// Residual + LayerNorm. mode 0: t = g_x + g_y, write g_x (in-place).
//                       mode 1: t = g_x, write outp (final LN).
// ---------------------------------------------------------------------------
__global__ __launch_bounds__(256) void add_ln(int mode,
                                              const float* __restrict__ gam,
                                              const float* __restrict__ beta,
                                              float* __restrict__ outp) {
    const int row = blockIdx.x;
    __shared__ float t[1024];
    __shared__ float red[8];
    const float* xr = g_x + (size_t)row * 1024;
    const float* yr = g_y + (size_t)row * 1024;
    const int tid = threadIdx.x;

    float lsum = 0.f;
#pragma unroll
    for (int i = 0; i < 4; i++) {
        int d = tid + i * 256;
        float v = xr[d] + (mode == 0 ? yr[d] : 0.f);
        t[d] = v;
        lsum += v;
    }
    float mu = blkSum(lsum, red) * (1.f / 1024.f);

    float lsq = 0.f;
#pragma unroll
    for (int i = 0; i < 4; i++) {
        int d = tid + i * 256;
        float dv = t[d] - mu;
        lsq += dv * dv;
    }
    float var = blkSum(lsq, red) * (1.f / 1024.f);
    float rinv = rsqrtf(var + 1e-5f);

    float* orow = (mode == 0) ? (g_x + (size_t)row * 1024) : (outp + (size_t)row * 1024);
#pragma unroll
    for (int i = 0; i < 4; i++) {
        int d = tid + i * 256;
        orow[d] = (t[d] - mu) * rinv * gam[d] + beta[d];
    }
}

// ---------------------------------------------------------------------------
// Launch
// ---------------------------------------------------------------------------
extern "C" void kernel_launch(void* const* d_in, const int* in_sizes, int n_in,
                              void* d_out, int out_size) {
    (void)in_sizes; (void)n_in; (void)out_size;
    const float* q  = (const float*)d_in[0];
    // d_in[1] = lens (unused in eval mode, matches reference)
    const float* Wq = (const float*)d_in[2];
    const float* bq = (const float*)d_in[3];
    const float* Wv = (const float*)d_in[4];
    const float* bv = (const float*)d_in[5];
    const float* Wo = (const float*)d_in[6];
    const float* bo = (const float*)d_in[7];
    const float* gm = (const float*)d_in[8];
    const float* lg = (const float*)d_in[9];
    const float* lb = (const float*)d_in[10];
    const float* fg = (const float*)d_in[11];
    const float* fb = (const float*)d_in[12];
    float* out = (float*)d_out;

    copy_in<<<(MR * DD) / 256, 256>>>(q);

    const dim3 gg(8, 16);
    for (int l = 0; l < LL; l++) {
        sgemm_bias<<<gg, 256>>>(0, Wq + (size_t)l * DD * DD, bq + l * DD);
        sgemm_bias<<<gg, 256>>>(1, Wv + (size_t)l * DD * DD, bv + l * DD);
        scores_kernel<<<dim3(16, 16, BB * HH), 256>>>();
        attn_kernel<<<dim3(SS, HH, BB), 256>>>(gm + l * HH);
        sgemm_bias<<<gg, 256>>>(2, Wo + (size_t)l * DD * DD, bo + l * DD);
        add_ln<<<MR, 256>>>(0, lg + l * DD, lb + l * DD, nullptr);
    }
    add_ln<<<MR, 256>>>(1, fg, fb, out);
}

// round 3
// speedup vs baseline: 1.0071x; 1.0071x over previous
#include <cuda_runtime.h>
#include <math.h>

// Problem constants
#define BB 2
#define SS 1024
#define DD 1024
#define HH 16
#define LL 4
#define DHH 64
#define MR 2048  // B*S

// Scratch (device globals; no allocation)
__device__ float g_x [MR * DD];
__device__ float g_qh[MR * DD];
__device__ float g_vh[MR * DD];
__device__ float g_ao[MR * DD];
__device__ float g_y [MR * DD];
__device__ float g_sc[(size_t)BB * HH * SS * SS];  // 128 MB

// ---------------------------------------------------------------------------
// Block reduction helpers (blockDim.x == 256 -> 8 warps)
// ---------------------------------------------------------------------------
__device__ __forceinline__ float blkMax(float v, float* red) {
    int lane = threadIdx.x & 31, w = threadIdx.x >> 5;
#pragma unroll
    for (int o = 16; o; o >>= 1) v = fmaxf(v, __shfl_xor_sync(0xffffffffu, v, o));
    if (lane == 0) red[w] = v;
    __syncthreads();
    float r = red[0];
#pragma unroll
    for (int i = 1; i < 8; i++) r = fmaxf(r, red[i]);
    __syncthreads();
    return r;
}

__device__ __forceinline__ float blkSum(float v, float* red) {
    int lane = threadIdx.x & 31, w = threadIdx.x >> 5;
#pragma unroll
    for (int o = 16; o; o >>= 1) v += __shfl_xor_sync(0xffffffffu, v, o);
    if (lane == 0) red[w] = v;
    __syncthreads();
    float r = 0.f;
#pragma unroll
    for (int i = 0; i < 8; i++) r += red[i];
    __syncthreads();
    return r;
}

// ---------------------------------------------------------------------------
// Copy input q -> g_x
// ---------------------------------------------------------------------------
__global__ void copy_in(const float* __restrict__ src) {
    int i = blockIdx.x * blockDim.x + threadIdx.x;
    g_x[i] = src[i];
}

// ---------------------------------------------------------------------------
// SGEMM + bias: C[2048,1024] = A[2048,1024] @ W[1024,1024] + bias
// mode: 0 -> A=g_x, C=g_qh ; 1 -> A=g_x, C=g_vh ; 2 -> A=g_ao, C=g_y
// 128x128 tile, BK=16, 256 threads, 8x8 micro-tile.
// ---------------------------------------------------------------------------
__global__ __launch_bounds__(256) void sgemm_bias(int mode,
                                                  const float* __restrict__ W,
                                                  const float* __restrict__ bias) {
    const float* A = (mode == 2) ? g_ao : g_x;
    float* C = (mode == 0) ? g_qh : (mode == 1) ? g_vh : g_y;

    const int m0 = blockIdx.y * 128, n0 = blockIdx.x * 128;
    __shared__ float As[128][17];
    __shared__ float Bs[16][128];

    const int tid = threadIdx.x, tx = tid & 15, ty = tid >> 4;
    float acc[8][8] = {};

    for (int k0 = 0; k0 < 1024; k0 += 16) {
#pragma unroll
        for (int i = 0; i < 8; i++) {
            int idx = tid + i * 256;
            int r = idx >> 4, c = idx & 15;
            As[r][c] = A[(size_t)(m0 + r) * 1024 + k0 + c];
        }
#pragma unroll
        for (int i = 0; i < 8; i++) {
            int idx = tid + i * 256;
            int r = idx >> 7, c = idx & 127;
            Bs[r][c] = W[(size_t)(k0 + r) * 1024 + n0 + c];
        }
        __syncthreads();
#pragma unroll
        for (int kk = 0; kk < 16; kk++) {
            float a[8], b[8];
#pragma unroll
            for (int i = 0; i < 8; i++) a[i] = As[ty * 8 + i][kk];
#pragma unroll
            for (int j = 0; j < 8; j++) b[j] = Bs[kk][tx * 8 + j];
#pragma unroll
            for (int i = 0; i < 8; i++)
#pragma unroll
                for (int j = 0; j < 8; j++) acc[i][j] += a[i] * b[j];
        }
        __syncthreads();
    }

#pragma unroll
    for (int i = 0; i < 8; i++) {
        int row = m0 + ty * 8 + i;
#pragma unroll
        for (int j = 0; j < 8; j++) {
            int col = n0 + tx * 8 + j;
            C[(size_t)row * 1024 + col] = acc[i][j] + bias[col];
        }
    }
}

// ---------------------------------------------------------------------------
// Scores: for each (b,h): S = Qh @ Qh^T / 8. 64x64 tiles; skip tiles strictly
// above the diagonal (never read by the causal attention kernel).
// ---------------------------------------------------------------------------
__global__ __launch_bounds__(256) void scores_kernel() {
    const int kt = blockIdx.x, qt = blockIdx.y, bh = blockIdx.z;
    if (kt > qt) return;
    const int b = bh >> 4, h = bh & 15;
    const int q0 = qt * 64, k0 = kt * 64;

    __shared__ float Qs[64][65];
    __shared__ float Ks[64][65];

    const int tid = threadIdx.x, tx = tid & 15, ty = tid >> 4;
    const float* qbase = g_qh + (size_t)(b * SS) * DD + h * DHH;

#pragma unroll
    for (int i = 0; i < 16; i++) {
        int idx = tid + i * 256;
        int r = idx >> 6, c = idx & 63;
        Qs[r][c] = qbase[(size_t)(q0 + r) * DD + c];
        Ks[r][c] = qbase[(size_t)(k0 + r) * DD + c];
    }
    __syncthreads();

    float acc[4][4] = {};
#pragma unroll 8
    for (int kk = 0; kk < 64; kk++) {
        float a[4], b2[4];
#pragma unroll
        for (int i = 0; i < 4; i++) a[i] = Qs[ty * 4 + i][kk];
#pragma unroll
        for (int j = 0; j < 4; j++) b2[j] = Ks[tx * 4 + j][kk];
#pragma unroll
        for (int i = 0; i < 4; i++)
#pragma unroll
            for (int j = 0; j < 4; j++) acc[i][j] += a[i] * b2[j];
    }

#pragma unroll
    for (int i = 0; i < 4; i++) {
        size_t rowoff = ((size_t)bh * SS + q0 + ty * 4 + i) * SS + k0;
#pragma unroll
        for (int j = 0; j < 4; j++)
            g_sc[rowoff + tx * 4 + j] = acc[i][j] * 0.125f;
    }
}

// ---------------------------------------------------------------------------
// Attention row kernel: one block per (b,h,q). 256 threads, 4 keys/thread.
// softmax -> cumsum scan -> distance decay -> softmax -> maxout -> PV
// ---------------------------------------------------------------------------
__global__ __launch_bounds__(256) void attn_kernel(const float* __restrict__ gam) {
    const int q = blockIdx.x, h = blockIdx.y, b = blockIdx.z;
    const int bh = b * HH + h;
    const int tid = threadIdx.x, lane = tid & 31, w = tid >> 5;

    float* aorow = g_ao + (size_t)(b * SS + q) * DD + h * DHH;
    const int nv = q;  // strict causal: keys 0..q-1
    if (nv == 0) {
        if (tid < 64) aorow[tid] = 0.f;
        return;
    }

    __shared__ float s_c[1024];
    __shared__ float red[8];
    __shared__ float pred[8][64];

    const float* srow = g_sc + ((size_t)bh * SS + q) * SS;
    const float gneg = -fabsf(gam[h]);
    const int k0 = tid * 4;

    float sv[4];
    bool val[4];
    float m1 = -3.0e38f;
#pragma unroll
    for (int i = 0; i < 4; i++) {
        int k = k0 + i;
        val[i] = (k < nv);
        sv[i] = val[i] ? srow[k] : 0.f;
        if (val[i]) m1 = fmaxf(m1, sv[i]);
    }
    m1 = blkMax(m1, red);

    float e[4];
#pragma unroll
    for (int i = 0; i < 4; i++) e[i] = val[i] ? expf(sv[i] - m1) : 0.f;

    // inclusive block scan over 1024 contiguous values (4 per thread)
    float l0 = e[0], l1 = l0 + e[1], l2 = l1 + e[2], l3 = l2 + e[3];
    float tot = l3, xs = tot;
#pragma unroll
    for (int o = 1; o < 32; o <<= 1) {
        float y = __shfl_up_sync(0xffffffffu, xs, o);
        if (lane >= o) xs += y;
    }
    if (lane == 31) red[w] = xs;
    __syncthreads();
    float woff = 0.f, sum1 = 0.f;
#pragma unroll
    for (int i = 0; i < 8; i++) {
        float t = red[i];
        sum1 += t;
        if (i < w) woff += t;
    }
    __syncthreads();
    const float exc = woff + xs - tot;
    float cum[4] = {exc + l0, exc + l1, exc + l2, exc + l3};

    const float rs = 1.f / sum1;
    float s2[4];
    float m2 = -3.0e38f;
#pragma unroll
    for (int i = 0; i < 4; i++) {
        if (val[i]) {
            float frac = fmaxf((sum1 - cum[i]) * rs, 0.f);
            float dist = sqrtf(frac * (float)(q - (k0 + i)));
            float eff = expf(dist * gneg);
            eff = fminf(fmaxf(eff, 1e-5f), 1e5f);
            s2[i] = sv[i] * eff;
            m2 = fmaxf(m2, s2[i]);
        } else {
            s2[i] = 0.f;
        }
    }
    m2 = blkMax(m2, red);

    float a[4], lsum = 0.f, lmax = 0.f;
#pragma unroll
    for (int i = 0; i < 4; i++) {
        a[i] = val[i] ? expf(s2[i] - m2) : 0.f;
        lsum += a[i];
        lmax = fmaxf(lmax, a[i]);
    }
    float sum2 = blkSum(lsum, red);
    float amax = blkMax(lmax, red);
    // scale = min(1/max(attn), 5); attn = a/sum2 -> coeff = a * min(sum2/amax,5)/sum2
    const float coef = fminf(sum2 / amax, 5.f) / sum2;
#pragma unroll
    for (int i = 0; i < 4; i++) s_c[k0 + i] = a[i] * coef;
    __syncthreads();

    // PV: each warp covers 128 keys; lane accumulates d=lane and d=lane+32
    float acc0 = 0.f, acc1 = 0.f;
    const int kb = w * 128;
    const int ke = min(kb + 128, nv);
    const float* vb = g_vh + (size_t)(b * SS) * DD + h * DHH + lane;
#pragma unroll 4
    for (int k = kb; k < ke; k++) {
        float c = s_c[k];
        const float* vr = vb + (size_t)k * DD;
        acc0 += c * vr[0];
        acc1 += c * vr[32];
    }
    pred[w][lane] = acc0;
    pred[w][lane + 32] = acc1;
    __syncthreads();
    if (tid < 64) {
        float s = 0.f;
#pragma unroll
        for (int i = 0; i < 8; i++) s += pred[i][tid];
        aorow[tid] = s;
    }
}

// ---------------------------------------------------------------------------
// Residual + LayerNorm. mode 0: t = g_x + g_y, write g_x (in-place).
//                       mode 1: t = g_x, write outp (final LN).
// ---------------------------------------------------------------------------
__global__ __launch_bounds__(256) void add_ln(int mode,
                                              const float* __restrict__ gam,
                                              const float* __restrict__ beta,
                                              float* __restrict__ outp) {
    const int row = blockIdx.x;
    __shared__ float t[1024];
    __shared__ float red[8];
    const float* xr = g_x + (size_t)row * 1024;
    const float* yr = g_y + (size_t)row * 1024;
    const int tid = threadIdx.x;

    float lsum = 0.f;
#pragma unroll
    for (int i = 0; i < 4; i++) {
        int d = tid + i * 256;
        float v = xr[d] + (mode == 0 ? yr[d] : 0.f);
        t[d] = v;
        lsum += v;
    }
    float mu = blkSum(lsum, red) * (1.f / 1024.f);

    float lsq = 0.f;
#pragma unroll
    for (int i = 0; i < 4; i++) {
        int d = tid + i * 256;
        float dv = t[d] - mu;
        lsq += dv * dv;
    }
    float var = blkSum(lsq, red) * (1.f / 1024.f);
    float rinv = rsqrtf(var + 1e-5f);

    float* orow = (mode == 0) ? (g_x + (size_t)row * 1024) : (outp + (size_t)row * 1024);
#pragma unroll
    for (int i = 0; i < 4; i++) {
        int d = tid + i * 256;
        orow[d] = (t[d] - mu) * rinv * gam[d] + beta[d];
    }
}

// ---------------------------------------------------------------------------
// Launch
// ---------------------------------------------------------------------------
extern "C" void kernel_launch(void* const* d_in, const int* in_sizes, int n_in,
                              void* d_out, int out_size) {
    (void)in_sizes; (void)n_in; (void)out_size;
    const float* q  = (const float*)d_in[0];
    // d_in[1] = lens (unused in eval mode, matches reference)
    const float* Wq = (const float*)d_in[2];
    const float* bq = (const float*)d_in[3];
    const float* Wv = (const float*)d_in[4];
    const float* bv = (const float*)d_in[5];
    const float* Wo = (const float*)d_in[6];
    const float* bo = (const float*)d_in[7];
    const float* gm = (const float*)d_in[8];
    const float* lg = (const float*)d_in[9];
    const float* lb = (const float*)d_in[10];
    const float* fg = (const float*)d_in[11];
    const float* fb = (const float*)d_in[12];
    float* out = (float*)d_out;

    copy_in<<<(MR * DD) / 256, 256>>>(q);

    const dim3 gg(8, 16);
    for (int l = 0; l < LL; l++) {
        sgemm_bias<<<gg, 256>>>(0, Wq + (size_t)l * DD * DD, bq + l * DD);
        sgemm_bias<<<gg, 256>>>(1, Wv + (size_t)l * DD * DD, bv + l * DD);
        scores_kernel<<<dim3(16, 16, BB * HH), 256>>>();
        attn_kernel<<<dim3(SS, HH, BB), 256>>>(gm + l * HH);
        sgemm_bias<<<gg, 256>>>(2, Wo + (size_t)l * DD * DD, bo + l * DD);
        add_ln<<<MR, 256>>>(0, lg + l * DD, lb + l * DD, nullptr);
    }
    add_ln<<<MR, 256>>>(1, fg, fb, out);
}

// round 4
// speedup vs baseline: 1.2252x; 1.2166x over previous
#include <cuda_runtime.h>
#include <math.h>
#include <stdint.h>

#define BB 2
#define SS 1024
#define DD 1024
#define HH 16
#define LL 4
#define DHH 64
#define MR 2048  // B*S

// Scratch (device globals; no allocation)
__device__ float g_x [MR * DD];
__device__ float g_qh[MR * DD];
__device__ float g_vh[MR * DD];
__device__ float g_ao[MR * DD];
__device__ float g_y [MR * DD];
__device__ float g_sc[(size_t)BB * HH * SS * SS];  // 128 MB

__device__ uint32_t g_wqh[LL * DD * DD], g_wql[LL * DD * DD];
__device__ uint32_t g_wvh[LL * DD * DD], g_wvl[LL * DD * DD];
__device__ uint32_t g_woh[LL * DD * DD], g_wol[LL * DD * DD];
__device__ uint32_t g_xh [MR * DD], g_xl [MR * DD];
__device__ uint32_t g_ph [MR * DD], g_pl [MR * DD];
__device__ uint32_t g_aoh[MR * DD], g_aol[MR * DD];

// ---------------------------------------------------------------------------
__device__ __forceinline__ void mma8(float c[4], const uint32_t a[4], const uint32_t b[2]) {
    asm volatile(
        "mma.sync.aligned.m16n8k8.row.col.f32.tf32.tf32.f32 "
        "{%0,%1,%2,%3}, {%4,%5,%6,%7}, {%8,%9}, {%0,%1,%2,%3};\n"
        : "+f"(c[0]), "+f"(c[1]), "+f"(c[2]), "+f"(c[3])
        : "r"(a[0]), "r"(a[1]), "r"(a[2]), "r"(a[3]), "r"(b[0]), "r"(b[1]));
}
__device__ __forceinline__ void cp16(uint32_t saddr, const void* g) {
    asm volatile("cp.async.cg.shared.global [%0], [%1], 16;\n" :: "r"(saddr), "l"(g));
}
__device__ __forceinline__ uint32_t f2tf(float x) {
    uint32_t r;
    asm("cvt.rna.tf32.f32 %0, %1;\n" : "=r"(r) : "f"(x));
    return r;
}
__device__ __forceinline__ float blkMax(float v, float* red) {
    int lane = threadIdx.x & 31, w = threadIdx.x >> 5;
#pragma unroll
    for (int o = 16; o; o >>= 1) v = fmaxf(v, __shfl_xor_sync(0xffffffffu, v, o));
    if (lane == 0) red[w] = v;
    __syncthreads();
    float r = red[0];
#pragma unroll
    for (int i = 1; i < 8; i++) r = fmaxf(r, red[i]);
    __syncthreads();
    return r;
}
__device__ __forceinline__ float blkSum(float v, float* red) {
    int lane = threadIdx.x & 31, w = threadIdx.x >> 5;
#pragma unroll
    for (int o = 16; o; o >>= 1) v += __shfl_xor_sync(0xffffffffu, v, o);
    if (lane == 0) red[w] = v;
    __syncthreads();
    float r = 0.f;
#pragma unroll
    for (int i = 0; i < 8; i++) r += red[i];
    __syncthreads();
    return r;
}

__global__ void copy_in(const float* __restrict__ src) {
    int i = blockIdx.x * blockDim.x + threadIdx.x;
    g_x[i] = src[i];
}

__global__ void split_tf32(const float* __restrict__ src, uint32_t* __restrict__ hi,
                           uint32_t* __restrict__ lo, int n) {
    int i = blockIdx.x * blockDim.x + threadIdx.x;
    if (i >= n) return;
    float x = src[i];
    uint32_t h = f2tf(x);
    hi[i] = h;
    lo[i] = f2tf(x - __uint_as_float(h));
}

// ---------------------------------------------------------------------------
// tf32 split GEMM: C[2048,1024] = A @ W + bias.  128x128 tile, BK=16,
// 128 threads (4 warps, 2x2 of 64x64), cp.async double-buffered.
// ---------------------------------------------------------------------------
#define G_AS  (128 * 20)
#define G_BS  (16 * 136)
#define G_STG (2 * G_AS + 2 * G_BS)

__device__ __forceinline__ void gemm_issue(uint32_t sbase, int s, int k0, int tid,
                                           int m0, int n0,
                                           const uint32_t* Ah, const uint32_t* Al,
                                           const uint32_t* Wh, const uint32_t* Wl) {
    uint32_t st = sbase + (uint32_t)(s * G_STG) * 4u;
#pragma unroll
    for (int i = 0; i < 4; i++) {
        int id = tid + i * 128;
        int m = id >> 2, kc = (id & 3) * 4;
        cp16(st + (uint32_t)(m * 20 + kc) * 4u, Ah + (size_t)(m0 + m) * 1024 + k0 + kc);
        cp16(st + (uint32_t)(G_AS + m * 20 + kc) * 4u, Al + (size_t)(m0 + m) * 1024 + k0 + kc);
    }
#pragma unroll
    for (int i = 0; i < 4; i++) {
        int id = tid + i * 128;
        int r = id >> 5, c = (id & 31) * 4;
        cp16(st + (uint32_t)(2 * G_AS + r * 136 + c) * 4u, Wh + (size_t)(k0 + r) * 1024 + n0 + c);
        cp16(st + (uint32_t)(2 * G_AS + G_BS + r * 136 + c) * 4u, Wl + (size_t)(k0 + r) * 1024 + n0 + c);
    }
    asm volatile("cp.async.commit_group;\n");
}

extern __shared__ uint32_t smdyn[];

__global__ __launch_bounds__(128) void gemm_tf32(
    const uint32_t* __restrict__ Ah, const uint32_t* __restrict__ Al,
    const uint32_t* __restrict__ Wh, const uint32_t* __restrict__ Wl,
    const float* __restrict__ bias, float* __restrict__ C) {
    const int tid = threadIdx.x;
    const int m0 = blockIdx.y * 128, n0 = blockIdx.x * 128;
    const int wid = tid >> 5, lane = tid & 31;
    const int wm = wid >> 1, wn = wid & 1;
    const int gid = lane >> 2, tg = lane & 3;

    float acc[4][8][4];
#pragma unroll
    for (int i = 0; i < 4; i++)
#pragma unroll
        for (int j = 0; j < 8; j++)
#pragma unroll
            for (int k = 0; k < 4; k++) acc[i][j][k] = 0.f;

    const uint32_t sbase = (uint32_t)__cvta_generic_to_shared(smdyn);
    gemm_issue(sbase, 0, 0, tid, m0, n0, Ah, Al, Wh, Wl);

    for (int kt = 0; kt < 64; kt++) {
        if (kt < 63) {
            gemm_issue(sbase, (kt + 1) & 1, (kt + 1) * 16, tid, m0, n0, Ah, Al, Wh, Wl);
            asm volatile("cp.async.wait_group 1;\n");
        } else {
            asm volatile("cp.async.wait_group 0;\n");
        }
        __syncthreads();

        const uint32_t* pS = smdyn + (kt & 1) * G_STG;
        const uint32_t* pAh = pS;
        const uint32_t* pAl = pS + G_AS;
        const uint32_t* pBh = pS + 2 * G_AS;
        const uint32_t* pBl = pS + 2 * G_AS + G_BS;

#pragma unroll
        for (int k8 = 0; k8 < 16; k8 += 8) {
            uint32_t afh[4][4], afl[4][4];
#pragma unroll
            for (int mt = 0; mt < 4; mt++) {
                int r = wm * 64 + mt * 16 + gid;
                int ka = k8 + tg;
                afh[mt][0] = pAh[r * 20 + ka];
                afh[mt][1] = pAh[(r + 8) * 20 + ka];
                afh[mt][2] = pAh[r * 20 + ka + 4];
                afh[mt][3] = pAh[(r + 8) * 20 + ka + 4];
                afl[mt][0] = pAl[r * 20 + ka];
                afl[mt][1] = pAl[(r + 8) * 20 + ka];
                afl[mt][2] = pAl[r * 20 + ka + 4];
                afl[mt][3] = pAl[(r + 8) * 20 + ka + 4];
            }
#pragma unroll
            for (int nt = 0; nt < 8; nt++) {
                int c = wn * 64 + nt * 8 + gid;
                int kb = k8 + tg;
                uint32_t bfh[2], bfl[2];
                bfh[0] = pBh[kb * 136 + c];
                bfh[1] = pBh[(kb + 4) * 136 + c];
                bfl[0] = pBl[kb * 136 + c];
                bfl[1] = pBl[(kb + 4) * 136 + c];
#pragma unroll
                for (int mt = 0; mt < 4; mt++) {
                    mma8(acc[mt][nt], afh[mt], bfh);
                    mma8(acc[mt][nt], afh[mt], bfl);
                    mma8(acc[mt][nt], afl[mt], bfh);
                }
            }
        }
        __syncthreads();
    }

#pragma unroll
    for (int mt = 0; mt < 4; mt++) {
        int r = m0 + wm * 64 + mt * 16 + gid;
#pragma unroll
        for (int nt = 0; nt < 8; nt++) {
            int c = n0 + wn * 64 + nt * 8 + 2 * tg;
            float b0 = bias[c], b1 = bias[c + 1];
            *(float2*)&C[(size_t)r * 1024 + c] =
                make_float2(acc[mt][nt][0] + b0, acc[mt][nt][1] + b1);
            *(float2*)&C[(size_t)(r + 8) * 1024 + c] =
                make_float2(acc[mt][nt][2] + b0, acc[mt][nt][3] + b1);
        }
    }
}

// ---------------------------------------------------------------------------
// Scores via tf32 split: S = Qh @ Qh^T / 8 per (b,h). 128x128 tiles,
// lower-triangular tiles only, K = 64 resident in smem.
// ---------------------------------------------------------------------------
__global__ __launch_bounds__(128) void scores_tf32(const uint32_t* __restrict__ Ph,
                                                   const uint32_t* __restrict__ Pl) {
    const int kt = blockIdx.x, qt = blockIdx.y;
    if (kt > qt) return;
    const int bh = blockIdx.z, b = bh >> 4, h = bh & 15;

    const int SZ = 128 * 68;
    uint32_t* sQh = smdyn;
    uint32_t* sQl = smdyn + SZ;
    uint32_t* sKh = smdyn + 2 * SZ;
    uint32_t* sKl = smdyn + 3 * SZ;

    const int tid = threadIdx.x;
#pragma unroll
    for (int i = 0; i < 16; i++) {
        int id = tid + i * 128;
        int m = id >> 4, c = (id & 15) * 4;
        size_t qoff = ((size_t)(b * SS + qt * 128 + m)) * 1024 + h * 64 + c;
        size_t koff = ((size_t)(b * SS + kt * 128 + m)) * 1024 + h * 64 + c;
        *(uint4*)&sQh[m * 68 + c] = *(const uint4*)(Ph + qoff);
        *(uint4*)&sQl[m * 68 + c] = *(const uint4*)(Pl + qoff);
        *(uint4*)&sKh[m * 68 + c] = *(const uint4*)(Ph + koff);
        *(uint4*)&sKl[m * 68 + c] = *(const uint4*)(Pl + koff);
    }
    __syncthreads();

    const int wid = tid >> 5, lane = tid & 31;
    const int wm = wid >> 1, wn = wid & 1;
    const int gid = lane >> 2, tg = lane & 3;

    float acc[4][8][4];
#pragma unroll
    for (int i = 0; i < 4; i++)
#pragma unroll
        for (int j = 0; j < 8; j++)
#pragma unroll
            for (int k = 0; k < 4; k++) acc[i][j][k] = 0.f;

#pragma unroll
    for (int k8 = 0; k8 < 64; k8 += 8) {
        uint32_t afh[4][4], afl[4][4];
#pragma unroll
        for (int mt = 0; mt < 4; mt++) {
            int r = wm * 64 + mt * 16 + gid;
            int ka = k8 + tg;
            afh[mt][0] = sQh[r * 68 + ka];
            afh[mt][1] = sQh[(r + 8) * 68 + ka];
            afh[mt][2] = sQh[r * 68 + ka + 4];
            afh[mt][3] = sQh[(r + 8) * 68 + ka + 4];
            afl[mt][0] = sQl[r * 68 + ka];
            afl[mt][1] = sQl[(r + 8) * 68 + ka];
            afl[mt][2] = sQl[r * 68 + ka + 4];
            afl[mt][3] = sQl[(r + 8) * 68 + ka + 4];
        }
#pragma unroll
        for (int nt = 0; nt < 8; nt++) {
            int n = wn * 64 + nt * 8 + gid;
            int kb = k8 + tg;
            uint32_t bfh[2], bfl[2];
            bfh[0] = sKh[n * 68 + kb];
            bfh[1] = sKh[n * 68 + kb + 4];
            bfl[0] = sKl[n * 68 + kb];
            bfl[1] = sKl[n * 68 + kb + 4];
#pragma unroll
            for (int mt = 0; mt < 4; mt++) {
                mma8(acc[mt][nt], afh[mt], bfh);
                mma8(acc[mt][nt], afh[mt], bfl);
                mma8(acc[mt][nt], afl[mt], bfh);
            }
        }
    }

#pragma unroll
    for (int mt = 0; mt < 4; mt++) {
        int row = qt * 128 + wm * 64 + mt * 16 + gid;
#pragma unroll
        for (int nt = 0; nt < 8; nt++) {
            int col = kt * 128 + wn * 64 + nt * 8 + 2 * tg;
            size_t off = ((size_t)bh * SS + row) * SS + col;
            *(float2*)&g_sc[off] =
                make_float2(acc[mt][nt][0] * 0.125f, acc[mt][nt][1] * 0.125f);
            *(float2*)&g_sc[off + 8 * SS] =
                make_float2(acc[mt][nt][2] * 0.125f, acc[mt][nt][3] * 0.125f);
        }
    }
}

// ---------------------------------------------------------------------------
// Attention row kernel (unchanged from passing baseline)
// ---------------------------------------------------------------------------
__global__ __launch_bounds__(256) void attn_kernel(const float* __restrict__ gam) {
    const int q = blockIdx.x, h = blockIdx.y, b = blockIdx.z;
    const int bh = b * HH + h;
    const int tid = threadIdx.x, lane = tid & 31, w = tid >> 5;

    float* aorow = g_ao + (size_t)(b * SS + q) * DD + h * DHH;
    const int nv = q;
    if (nv == 0) {
        if (tid < 64) aorow[tid] = 0.f;
        return;
    }

    __shared__ float s_c[1024];
    __shared__ float red[8];
    __shared__ float pred[8][64];

    const float* srow = g_sc + ((size_t)bh * SS + q) * SS;
    const float gneg = -fabsf(gam[h]);
    const int k0 = tid * 4;

    float sv[4];
    bool val[4];
    float m1 = -3.0e38f;
#pragma unroll
    for (int i = 0; i < 4; i++) {
        int k = k0 + i;
        val[i] = (k < nv);
        sv[i] = val[i] ? srow[k] : 0.f;
        if (val[i]) m1 = fmaxf(m1, sv[i]);
    }
    m1 = blkMax(m1, red);

    float e[4];
#pragma unroll
    for (int i = 0; i < 4; i++) e[i] = val[i] ? expf(sv[i] - m1) : 0.f;

    float l0 = e[0], l1 = l0 + e[1], l2 = l1 + e[2], l3 = l2 + e[3];
    float tot = l3, xs = tot;
#pragma unroll
    for (int o = 1; o < 32; o <<= 1) {
        float y = __shfl_up_sync(0xffffffffu, xs, o);
        if (lane >= o) xs += y;
    }
    if (lane == 31) red[w] = xs;
    __syncthreads();
    float woff = 0.f, sum1 = 0.f;
#pragma unroll
    for (int i = 0; i < 8; i++) {
        float t = red[i];
        sum1 += t;
        if (i < w) woff += t;
    }
    __syncthreads();
    const float exc = woff + xs - tot;
    float cum[4] = {exc + l0, exc + l1, exc + l2, exc + l3};

    const float rs = 1.f / sum1;
    float s2[4];
    float m2 = -3.0e38f;
#pragma unroll
    for (int i = 0; i < 4; i++) {
        if (val[i]) {
            float frac = fmaxf((sum1 - cum[i]) * rs, 0.f);
            float dist = sqrtf(frac * (float)(q - (k0 + i)));
            float eff = expf(dist * gneg);
            eff = fminf(fmaxf(eff, 1e-5f), 1e5f);
            s2[i] = sv[i] * eff;
            m2 = fmaxf(m2, s2[i]);
        } else {
            s2[i] = 0.f;
        }
    }
    m2 = blkMax(m2, red);

    float a[4], lsum = 0.f, lmax = 0.f;
#pragma unroll
    for (int i = 0; i < 4; i++) {
        a[i] = val[i] ? expf(s2[i] - m2) : 0.f;
        lsum += a[i];
        lmax = fmaxf(lmax, a[i]);
    }
    float sum2 = blkSum(lsum, red);
    float amax = blkMax(lmax, red);
    const float coef = fminf(sum2 / amax, 5.f) / sum2;
#pragma unroll
    for (int i = 0; i < 4; i++) s_c[k0 + i] = a[i] * coef;
    __syncthreads();

    float acc0 = 0.f, acc1 = 0.f;
    const int kb = w * 128;
    const int ke = min(kb + 128, nv);
    const float* vb = g_vh + (size_t)(b * SS) * DD + h * DHH + lane;
#pragma unroll 4
    for (int k = kb; k < ke; k++) {
        float c = s_c[k];
        const float* vr = vb + (size_t)k * DD;
        acc0 += c * vr[0];
        acc1 += c * vr[32];
    }
    pred[w][lane] = acc0;
    pred[w][lane + 32] = acc1;
    __syncthreads();
    if (tid < 64) {
        float s = 0.f;
#pragma unroll
        for (int i = 0; i < 8; i++) s += pred[i][tid];
        aorow[tid] = s;
    }
}

// ---------------------------------------------------------------------------
// Residual + LayerNorm (unchanged)
// ---------------------------------------------------------------------------
__global__ __launch_bounds__(256) void add_ln(int mode,
                                              const float* __restrict__ gam,
                                              const float* __restrict__ beta,
                                              float* __restrict__ outp) {
    const int row = blockIdx.x;
    __shared__ float t[1024];
    __shared__ float red[8];
    const float* xr = g_x + (size_t)row * 1024;
    const float* yr = g_y + (size_t)row * 1024;
    const int tid = threadIdx.x;

    float lsum = 0.f;
#pragma unroll
    for (int i = 0; i < 4; i++) {
        int d = tid + i * 256;
        float v = xr[d] + (mode == 0 ? yr[d] : 0.f);
        t[d] = v;
        lsum += v;
    }
    float mu = blkSum(lsum, red) * (1.f / 1024.f);

    float lsq = 0.f;
#pragma unroll
    for (int i = 0; i < 4; i++) {
        int d = tid + i * 256;
        float dv = t[d] - mu;
        lsq += dv * dv;
    }
    float var = blkSum(lsq, red) * (1.f / 1024.f);
    float rinv = rsqrtf(var + 1e-5f);

    float* orow = (mode == 0) ? (g_x + (size_t)row * 1024) : (outp + (size_t)row * 1024);
#pragma unroll
    for (int i = 0; i < 4; i++) {
        int d = tid + i * 256;
        orow[d] = (t[d] - mu) * rinv * gam[d] + beta[d];
    }
}

// ---------------------------------------------------------------------------
// Launch
// ---------------------------------------------------------------------------
extern "C" void kernel_launch(void* const* d_in, const int* in_sizes, int n_in,
                              void* d_out, int out_size) {
    (void)in_sizes; (void)n_in; (void)out_size;
    const float* q  = (const float*)d_in[0];
    const float* Wq = (const float*)d_in[2];
    const float* bq = (const float*)d_in[3];
    const float* Wv = (const float*)d_in[4];
    const float* bv = (const float*)d_in[5];
    const float* Wo = (const float*)d_in[6];
    const float* bo = (const float*)d_in[7];
    const float* gm = (const float*)d_in[8];
    const float* lg = (const float*)d_in[9];
    const float* lb = (const float*)d_in[10];
    const float* fg = (const float*)d_in[11];
    const float* fb = (const float*)d_in[12];
    float* out = (float*)d_out;

    static int smem_set = 0;
    const int GEMM_SMEM = 2 * G_STG * 4;          // 75776 B
    const int SC_SMEM = 4 * 128 * 68 * 4;         // 139264 B
    if (!smem_set) {
        cudaFuncSetAttribute(gemm_tf32, cudaFuncAttributeMaxDynamicSharedMemorySize, GEMM_SMEM);
        cudaFuncSetAttribute(scores_tf32, cudaFuncAttributeMaxDynamicSharedMemorySize, SC_SMEM);
        smem_set = 1;
    }

    // Resolve device-global addresses (host side)
    uint32_t *wqh, *wql, *wvh, *wvl, *woh, *wol, *xh, *xl, *ph, *pl, *aoh, *aol;
    cudaGetSymbolAddress((void**)&wqh, g_wqh); cudaGetSymbolAddress((void**)&wql, g_wql);
    cudaGetSymbolAddress((void**)&wvh, g_wvh); cudaGetSymbolAddress((void**)&wvl, g_wvl);
    cudaGetSymbolAddress((void**)&woh, g_woh); cudaGetSymbolAddress((void**)&wol, g_wol);
    cudaGetSymbolAddress((void**)&xh, g_xh);   cudaGetSymbolAddress((void**)&xl, g_xl);
    cudaGetSymbolAddress((void**)&ph, g_ph);   cudaGetSymbolAddress((void**)&pl, g_pl);
    cudaGetSymbolAddress((void**)&aoh, g_aoh); cudaGetSymbolAddress((void**)&aol, g_aol);
    float *qhp, *vhp, *yp;
    cudaGetSymbolAddress((void**)&qhp, g_qh);
    cudaGetSymbolAddress((void**)&vhp, g_vh);
    cudaGetSymbolAddress((void**)&yp, g_y);

    copy_in<<<(MR * DD) / 256, 256>>>(q);

    const int NW = LL * DD * DD;                  // 4M
    split_tf32<<<NW / 256, 256>>>(Wq, wqh, wql, NW);
    split_tf32<<<NW / 256, 256>>>(Wv, wvh, wvl, NW);
    split_tf32<<<NW / 256, 256>>>(Wo, woh, wol, NW);

    const int NA = MR * DD;                       // 2M
    const dim3 gg(8, 16);
    float* gx; cudaGetSymbolAddress((void**)&gx, g_x);
    float* gao; cudaGetSymbolAddress((void**)&gao, g_ao);

    for (int l = 0; l < LL; l++) {
        size_t wo = (size_t)l * DD * DD;
        split_tf32<<<NA / 256, 256>>>(gx, xh, xl, NA);
        gemm_tf32<<<gg, 128, GEMM_SMEM>>>(xh, xl, wqh + wo, wql + wo, bq + l * DD, qhp);
        gemm_tf32<<<gg, 128, GEMM_SMEM>>>(xh, xl, wvh + wo, wvl + wo, bv + l * DD, vhp);
        split_tf32<<<NA / 256, 256>>>(qhp, ph, pl, NA);
        scores_tf32<<<dim3(8, 8, BB * HH), 128, SC_SMEM>>>(ph, pl);
        attn_kernel<<<dim3(SS, HH, BB), 256>>>(gm + l * HH);
        split_tf32<<<NA / 256, 256>>>(gao, aoh, aol, NA);
        gemm_tf32<<<gg, 128, GEMM_SMEM>>>(aoh, aol, woh + wo, wol + wo, bo + l * DD, yp);
        add_ln<<<MR, 256>>>(0, lg + l * DD, lb + l * DD, nullptr);
    }
    add_ln<<<MR, 256>>>(1, fg, fb, out);
}

// round 5
// speedup vs baseline: 1.6296x; 1.3300x over previous
#include <cuda_runtime.h>
#include <cuda_bf16.h>
#include <math.h>
#include <stdint.h>

#define BB 2
#define SS 1024
#define DD 1024
#define HH 16
#define LL 4
#define DHH 64
#define MR 2048  // B*S

// ---------------------------------------------------------------------------
// Scratch (device globals; no allocation)
// ---------------------------------------------------------------------------
__device__ float g_x [MR * DD];
__device__ float g_vh[MR * DD];
__device__ float g_y [MR * DD];
__device__ float g_sc[(size_t)BB * HH * SS * SS];  // 128 MB

__device__ __nv_bfloat16 g_xh [MR * DD], g_xl [MR * DD];
__device__ __nv_bfloat16 g_qph[MR * DD], g_qpl[MR * DD];
__device__ __nv_bfloat16 g_aoh[MR * DD], g_aol[MR * DD];

// packed weights: [l][kp][n] u32 = (bf16 W[2kp][n], bf16 W[2kp+1][n])
#define WPK (LL * 512 * DD)
__device__ uint32_t g_wq_h[WPK], g_wq_l[WPK];
__device__ uint32_t g_wv_h[WPK], g_wv_l[WPK];
__device__ uint32_t g_wo_h[WPK], g_wo_l[WPK];

// ---------------------------------------------------------------------------
__device__ __forceinline__ void mma16(float c[4], const uint32_t a[4], const uint32_t b[2]) {
    asm volatile(
        "mma.sync.aligned.m16n8k16.row.col.f32.bf16.bf16.f32 "
        "{%0,%1,%2,%3}, {%4,%5,%6,%7}, {%8,%9}, {%0,%1,%2,%3};\n"
        : "+f"(c[0]), "+f"(c[1]), "+f"(c[2]), "+f"(c[3])
        : "r"(a[0]), "r"(a[1]), "r"(a[2]), "r"(a[3]), "r"(b[0]), "r"(b[1]));
}
__device__ __forceinline__ void cp16(uint32_t saddr, const void* g) {
    asm volatile("cp.async.cg.shared.global [%0], [%1], 16;\n" :: "r"(saddr), "l"(g));
}
__device__ __forceinline__ uint16_t bfbits(__nv_bfloat16 b) {
    return *(uint16_t*)&b;
}
__device__ __forceinline__ void split2(float v0, float v1, uint32_t& hi, uint32_t& lo) {
    __nv_bfloat16 h0 = __float2bfloat16_rn(v0), h1 = __float2bfloat16_rn(v1);
    __nv_bfloat16 l0 = __float2bfloat16_rn(v0 - __bfloat162float(h0));
    __nv_bfloat16 l1 = __float2bfloat16_rn(v1 - __bfloat162float(h1));
    hi = (uint32_t)bfbits(h0) | ((uint32_t)bfbits(h1) << 16);
    lo = (uint32_t)bfbits(l0) | ((uint32_t)bfbits(l1) << 16);
}
__device__ __forceinline__ float blkMax(float v, float* red) {
    int lane = threadIdx.x & 31, w = threadIdx.x >> 5;
#pragma unroll
    for (int o = 16; o; o >>= 1) v = fmaxf(v, __shfl_xor_sync(0xffffffffu, v, o));
    if (lane == 0) red[w] = v;
    __syncthreads();
    float r = red[0];
#pragma unroll
    for (int i = 1; i < 8; i++) r = fmaxf(r, red[i]);
    __syncthreads();
    return r;
}
__device__ __forceinline__ float blkSum(float v, float* red) {
    int lane = threadIdx.x & 31, w = threadIdx.x >> 5;
#pragma unroll
    for (int o = 16; o; o >>= 1) v += __shfl_xor_sync(0xffffffffu, v, o);
    if (lane == 0) red[w] = v;
    __syncthreads();
    float r = 0.f;
#pragma unroll
    for (int i = 0; i < 8; i++) r += red[i];
    __syncthreads();
    return r;
}

// ---------------------------------------------------------------------------
// copy input q -> g_x + bf16 split
// ---------------------------------------------------------------------------
__global__ void copy_in_split(const float* __restrict__ src) {
    int i = blockIdx.x * blockDim.x + threadIdx.x;
    float x = src[i];
    g_x[i] = x;
    __nv_bfloat16 h = __float2bfloat16_rn(x);
    g_xh[i] = h;
    g_xl[i] = __float2bfloat16_rn(x - __bfloat162float(h));
}

// ---------------------------------------------------------------------------
// pack weights: pairs along k. idx = l*512*1024 + kp*1024 + n
// ---------------------------------------------------------------------------
__global__ void pack_w(const float* __restrict__ W, uint32_t* __restrict__ ph,
                       uint32_t* __restrict__ pl) {
    int idx = blockIdx.x * blockDim.x + threadIdx.x;
    int l = idx >> 19;
    int rem = idx & ((1 << 19) - 1);
    int kp = rem >> 10, n = rem & 1023;
    size_t base = (size_t)l * DD * DD;
    float f0 = W[base + (size_t)(2 * kp) * DD + n];
    float f1 = W[base + (size_t)(2 * kp + 1) * DD + n];
    uint32_t hi, lo;
    split2(f0, f1, hi, lo);
    ph[idx] = hi;
    pl[idx] = lo;
}

// ---------------------------------------------------------------------------
// bf16 split GEMM: C[2048,1024] = A @ W + bias.  128x128 tile, BK=32 (16 u32),
// 128 threads (4 warps, 2x2 of 64x64), cp.async double-buffered.
// outmode 0: fp32 to Cf;  1: bf16 hi/lo split to Oh/Ol.
// ---------------------------------------------------------------------------
#define G_AS  (128 * 20)
#define G_BS  (16 * 136)
#define G_STG (2 * G_AS + 2 * G_BS)

extern __shared__ uint32_t smdyn[];

__device__ __forceinline__ void gemm_issue(uint32_t sbase, int s, int kp0, int tid,
                                           int m0, int n0,
                                           const uint32_t* Ah, const uint32_t* Al,
                                           const uint32_t* Wh, const uint32_t* Wl) {
    uint32_t st = sbase + (uint32_t)(s * G_STG) * 4u;
#pragma unroll
    for (int i = 0; i < 4; i++) {
        int id = tid + i * 128;
        int m = id >> 2, kc = (id & 3) * 4;
        cp16(st + (uint32_t)(m * 20 + kc) * 4u, Ah + (size_t)(m0 + m) * 512 + kp0 + kc);
        cp16(st + (uint32_t)(G_AS + m * 20 + kc) * 4u, Al + (size_t)(m0 + m) * 512 + kp0 + kc);
    }
#pragma unroll
    for (int i = 0; i < 4; i++) {
        int id = tid + i * 128;
        int r = id >> 5, c = (id & 31) * 4;
        cp16(st + (uint32_t)(2 * G_AS + r * 136 + c) * 4u, Wh + (size_t)(kp0 + r) * 1024 + n0 + c);
        cp16(st + (uint32_t)(2 * G_AS + G_BS + r * 136 + c) * 4u, Wl + (size_t)(kp0 + r) * 1024 + n0 + c);
    }
    asm volatile("cp.async.commit_group;\n");
}

__global__ __launch_bounds__(128) void gemm_bf16(
    const uint32_t* __restrict__ Ah, const uint32_t* __restrict__ Al,
    const uint32_t* __restrict__ Wh, const uint32_t* __restrict__ Wl,
    const float* __restrict__ bias, int outmode, float* __restrict__ Cf,
    __nv_bfloat16* __restrict__ Oh, __nv_bfloat16* __restrict__ Ol) {
    const int tid = threadIdx.x;
    const int m0 = blockIdx.y * 128, n0 = blockIdx.x * 128;
    const int wid = tid >> 5, lane = tid & 31;
    const int wm = wid >> 1, wn = wid & 1;
    const int gid = lane >> 2, tg = lane & 3;

    float acc[4][8][4];
#pragma unroll
    for (int i = 0; i < 4; i++)
#pragma unroll
        for (int j = 0; j < 8; j++)
#pragma unroll
            for (int k = 0; k < 4; k++) acc[i][j][k] = 0.f;

    const uint32_t sbase = (uint32_t)__cvta_generic_to_shared(smdyn);
    gemm_issue(sbase, 0, 0, tid, m0, n0, Ah, Al, Wh, Wl);

    for (int kt = 0; kt < 32; kt++) {
        if (kt < 31) {
            gemm_issue(sbase, (kt + 1) & 1, (kt + 1) * 16, tid, m0, n0, Ah, Al, Wh, Wl);
            asm volatile("cp.async.wait_group 1;\n");
        } else {
            asm volatile("cp.async.wait_group 0;\n");
        }
        __syncthreads();

        const uint32_t* pS = smdyn + (kt & 1) * G_STG;
        const uint32_t* pAh = pS;
        const uint32_t* pAl = pS + G_AS;
        const uint32_t* pBh = pS + 2 * G_AS;
        const uint32_t* pBl = pS + 2 * G_AS + G_BS;

#pragma unroll
        for (int kpb = 0; kpb < 16; kpb += 8) {
            uint32_t afh[4][4], afl[4][4];
#pragma unroll
            for (int mt = 0; mt < 4; mt++) {
                int r = wm * 64 + mt * 16 + gid;
                afh[mt][0] = pAh[r * 20 + kpb + tg];
                afh[mt][1] = pAh[(r + 8) * 20 + kpb + tg];
                afh[mt][2] = pAh[r * 20 + kpb + 4 + tg];
                afh[mt][3] = pAh[(r + 8) * 20 + kpb + 4 + tg];
                afl[mt][0] = pAl[r * 20 + kpb + tg];
                afl[mt][1] = pAl[(r + 8) * 20 + kpb + tg];
                afl[mt][2] = pAl[r * 20 + kpb + 4 + tg];
                afl[mt][3] = pAl[(r + 8) * 20 + kpb + 4 + tg];
            }
#pragma unroll
            for (int nt = 0; nt < 8; nt++) {
                int c = wn * 64 + nt * 8 + gid;
                uint32_t bfh[2], bfl[2];
                bfh[0] = pBh[(kpb + tg) * 136 + c];
                bfh[1] = pBh[(kpb + 4 + tg) * 136 + c];
                bfl[0] = pBl[(kpb + tg) * 136 + c];
                bfl[1] = pBl[(kpb + 4 + tg) * 136 + c];
#pragma unroll
                for (int mt = 0; mt < 4; mt++) {
                    mma16(acc[mt][nt], afh[mt], bfh);
                    mma16(acc[mt][nt], afh[mt], bfl);
                    mma16(acc[mt][nt], afl[mt], bfh);
                }
            }
        }
        __syncthreads();
    }

#pragma unroll
    for (int mt = 0; mt < 4; mt++) {
        int r = m0 + wm * 64 + mt * 16 + gid;
#pragma unroll
        for (int nt = 0; nt < 8; nt++) {
            int c = n0 + wn * 64 + nt * 8 + 2 * tg;
            float b0 = bias[c], b1 = bias[c + 1];
            float v0 = acc[mt][nt][0] + b0, v1 = acc[mt][nt][1] + b1;
            float v2 = acc[mt][nt][2] + b0, v3 = acc[mt][nt][3] + b1;
            if (outmode == 0) {
                *(float2*)&Cf[(size_t)r * 1024 + c] = make_float2(v0, v1);
                *(float2*)&Cf[(size_t)(r + 8) * 1024 + c] = make_float2(v2, v3);
            } else {
                uint32_t hi, lo;
                split2(v0, v1, hi, lo);
                *(uint32_t*)&Oh[(size_t)r * 1024 + c] = hi;
                *(uint32_t*)&Ol[(size_t)r * 1024 + c] = lo;
                split2(v2, v3, hi, lo);
                *(uint32_t*)&Oh[(size_t)(r + 8) * 1024 + c] = hi;
                *(uint32_t*)&Ol[(size_t)(r + 8) * 1024 + c] = lo;
            }
        }
    }
}

// ---------------------------------------------------------------------------
// Scores via bf16 split: S = Qh @ Qh^T / 8 per (b,h). 128x128 tiles,
// lower-triangular tiles only, 64 dh resident in smem (32 u32/row).
// ---------------------------------------------------------------------------
__global__ __launch_bounds__(128) void scores_bf16(const uint32_t* __restrict__ Ph,
                                                   const uint32_t* __restrict__ Pl) {
    const int kt = blockIdx.x, qt = blockIdx.y;
    if (kt > qt) return;
    const int bh = blockIdx.z, b = bh >> 4, h = bh & 15;

    const int SZ = 128 * 36;
    uint32_t* sQh = smdyn;
    uint32_t* sQl = smdyn + SZ;
    uint32_t* sKh = smdyn + 2 * SZ;
    uint32_t* sKl = smdyn + 3 * SZ;

    const int tid = threadIdx.x;
#pragma unroll
    for (int i = 0; i < 8; i++) {
        int id = tid + i * 128;
        int m = id >> 3, c = (id & 7) * 4;
        size_t qoff = (size_t)(b * SS + qt * 128 + m) * 512 + h * 32 + c;
        size_t koff = (size_t)(b * SS + kt * 128 + m) * 512 + h * 32 + c;
        *(uint4*)&sQh[m * 36 + c] = *(const uint4*)(Ph + qoff);
        *(uint4*)&sQl[m * 36 + c] = *(const uint4*)(Pl + qoff);
        *(uint4*)&sKh[m * 36 + c] = *(const uint4*)(Ph + koff);
        *(uint4*)&sKl[m * 36 + c] = *(const uint4*)(Pl + koff);
    }
    __syncthreads();

    const int wid = tid >> 5, lane = tid & 31;
    const int wm = wid >> 1, wn = wid & 1;
    const int gid = lane >> 2, tg = lane & 3;

    float acc[4][8][4];
#pragma unroll
    for (int i = 0; i < 4; i++)
#pragma unroll
        for (int j = 0; j < 8; j++)
#pragma unroll
            for (int k = 0; k < 4; k++) acc[i][j][k] = 0.f;

#pragma unroll
    for (int kpb = 0; kpb < 32; kpb += 8) {
        uint32_t afh[4][4], afl[4][4];
#pragma unroll
        for (int mt = 0; mt < 4; mt++) {
            int r = wm * 64 + mt * 16 + gid;
            afh[mt][0] = sQh[r * 36 + kpb + tg];
            afh[mt][1] = sQh[(r + 8) * 36 + kpb + tg];
            afh[mt][2] = sQh[r * 36 + kpb + 4 + tg];
            afh[mt][3] = sQh[(r + 8) * 36 + kpb + 4 + tg];
            afl[mt][0] = sQl[r * 36 + kpb + tg];
            afl[mt][1] = sQl[(r + 8) * 36 + kpb + tg];
            afl[mt][2] = sQl[r * 36 + kpb + 4 + tg];
            afl[mt][3] = sQl[(r + 8) * 36 + kpb + 4 + tg];
        }
#pragma unroll
        for (int nt = 0; nt < 8; nt++) {
            int n = wn * 64 + nt * 8 + gid;
            uint32_t bfh[2], bfl[2];
            bfh[0] = sKh[n * 36 + kpb + tg];
            bfh[1] = sKh[n * 36 + kpb + 4 + tg];
            bfl[0] = sKl[n * 36 + kpb + tg];
            bfl[1] = sKl[n * 36 + kpb + 4 + tg];
#pragma unroll
            for (int mt = 0; mt < 4; mt++) {
                mma16(acc[mt][nt], afh[mt], bfh);
                mma16(acc[mt][nt], afh[mt], bfl);
                mma16(acc[mt][nt], afl[mt], bfh);
            }
        }
    }

#pragma unroll
    for (int mt = 0; mt < 4; mt++) {
        int row = qt * 128 + wm * 64 + mt * 16 + gid;
#pragma unroll
        for (int nt = 0; nt < 8; nt++) {
            int col = kt * 128 + wn * 64 + nt * 8 + 2 * tg;
            size_t off = ((size_t)bh * SS + row) * SS + col;
            *(float2*)&g_sc[off] =
                make_float2(acc[mt][nt][0] * 0.125f, acc[mt][nt][1] * 0.125f);
            *(float2*)&g_sc[off + 8 * SS] =
                make_float2(acc[mt][nt][2] * 0.125f, acc[mt][nt][3] * 0.125f);
        }
    }
}

// ---------------------------------------------------------------------------
// Attention row kernel: __expf fast path, amax == 1 identity, split output.
// ---------------------------------------------------------------------------
__global__ __launch_bounds__(256) void attn_kernel(const float* __restrict__ gam) {
    const int q = blockIdx.x, h = blockIdx.y, b = blockIdx.z;
    const int bh = b * HH + h;
    const int tid = threadIdx.x, lane = tid & 31, w = tid >> 5;

    const size_t aoff = (size_t)(b * SS + q) * DD + h * DHH;
    const int nv = q;
    if (nv == 0) {
        if (tid < 64) {
            g_aoh[aoff + tid] = __float2bfloat16_rn(0.f);
            g_aol[aoff + tid] = __float2bfloat16_rn(0.f);
        }
        return;
    }

    __shared__ float s_c[1024];
    __shared__ float red[8];
    __shared__ float pred[8][64];

    const float* srow = g_sc + ((size_t)bh * SS + q) * SS;
    const float gneg = -fabsf(gam[h]);
    const int k0 = tid * 4;

    float sv[4];
    bool val[4];
    float m1 = -3.0e38f;
#pragma unroll
    for (int i = 0; i < 4; i++) {
        int k = k0 + i;
        val[i] = (k < nv);
        sv[i] = val[i] ? srow[k] : 0.f;
        if (val[i]) m1 = fmaxf(m1, sv[i]);
    }
    m1 = blkMax(m1, red);

    float e[4];
#pragma unroll
    for (int i = 0; i < 4; i++) e[i] = val[i] ? __expf(sv[i] - m1) : 0.f;

    float l0 = e[0], l1 = l0 + e[1], l2 = l1 + e[2], l3 = l2 + e[3];
    float tot = l3, xs = tot;
#pragma unroll
    for (int o = 1; o < 32; o <<= 1) {
        float y = __shfl_up_sync(0xffffffffu, xs, o);
        if (lane >= o) xs += y;
    }
    if (lane == 31) red[w] = xs;
    __syncthreads();
    float woff = 0.f, sum1 = 0.f;
#pragma unroll
    for (int i = 0; i < 8; i++) {
        float t = red[i];
        sum1 += t;
        if (i < w) woff += t;
    }
    __syncthreads();
    const float exc = woff + xs - tot;
    float cum[4] = {exc + l0, exc + l1, exc + l2, exc + l3};

    const float rs = __fdividef(1.f, sum1);
    float s2[4];
    float m2 = -3.0e38f;
#pragma unroll
    for (int i = 0; i < 4; i++) {
        if (val[i]) {
            float frac = fmaxf((sum1 - cum[i]) * rs, 0.f);
            float dist = sqrtf(frac * (float)(q - (k0 + i)));
            float eff = __expf(dist * gneg);
            eff = fminf(fmaxf(eff, 1e-5f), 1e5f);
            s2[i] = sv[i] * eff;
            m2 = fmaxf(m2, s2[i]);
        } else {
            s2[i] = 0.f;
        }
    }
    m2 = blkMax(m2, red);

    float a[4], lsum = 0.f;
#pragma unroll
    for (int i = 0; i < 4; i++) {
        a[i] = val[i] ? __expf(s2[i] - m2) : 0.f;
        lsum += a[i];
    }
    float sum2 = blkSum(lsum, red);
    // max attn weight = exp(0)/sum2 = 1/sum2 -> scale = min(sum2, 5)
    const float coef = __fdividef(fminf(sum2, 5.f), sum2);
#pragma unroll
    for (int i = 0; i < 4; i++) s_c[k0 + i] = a[i] * coef;
    __syncthreads();

    float acc0 = 0.f, acc1 = 0.f;
    const int kb = w * 128;
    const int ke = min(kb + 128, nv);
    const float* vb = g_vh + (size_t)(b * SS) * DD + h * DHH + lane;
#pragma unroll 4
    for (int k = kb; k < ke; k++) {
        float c = s_c[k];
        const float* vr = vb + (size_t)k * DD;
        acc0 += c * vr[0];
        acc1 += c * vr[32];
    }
    pred[w][lane] = acc0;
    pred[w][lane + 32] = acc1;
    __syncthreads();
    if (tid < 64) {
        float s = 0.f;
#pragma unroll
        for (int i = 0; i < 8; i++) s += pred[i][tid];
        __nv_bfloat16 hb = __float2bfloat16_rn(s);
        g_aoh[aoff + tid] = hb;
        g_aol[aoff + tid] = __float2bfloat16_rn(s - __bfloat162float(hb));
    }
}

// ---------------------------------------------------------------------------
// Residual + LayerNorm. mode 0: g_x = LN(g_x + g_y), plus bf16 split.
//                       mode 1: outp = LN(g_x) (final).
// ---------------------------------------------------------------------------
__global__ __launch_bounds__(256) void add_ln(int mode,
                                              const float* __restrict__ gam,
                                              const float* __restrict__ beta,
                                              float* __restrict__ outp) {
    const int row = blockIdx.x;
    __shared__ float t[1024];
    __shared__ float red[8];
    const float* xr = g_x + (size_t)row * 1024;
    const float* yr = g_y + (size_t)row * 1024;
    const int tid = threadIdx.x;

    float lsum = 0.f;
#pragma unroll
    for (int i = 0; i < 4; i++) {
        int d = tid + i * 256;
        float v = xr[d] + (mode == 0 ? yr[d] : 0.f);
        t[d] = v;
        lsum += v;
    }
    float mu = blkSum(lsum, red) * (1.f / 1024.f);

    float lsq = 0.f;
#pragma unroll
    for (int i = 0; i < 4; i++) {
        int d = tid + i * 256;
        float dv = t[d] - mu;
        lsq += dv * dv;
    }
    float var = blkSum(lsq, red) * (1.f / 1024.f);
    float rinv = rsqrtf(var + 1e-5f);

#pragma unroll
    for (int i = 0; i < 4; i++) {
        int d = tid + i * 256;
        float v = (t[d] - mu) * rinv * gam[d] + beta[d];
        size_t off = (size_t)row * 1024 + d;
        if (mode == 0) {
            g_x[off] = v;
            __nv_bfloat16 hb = __float2bfloat16_rn(v);
            g_xh[off] = hb;
            g_xl[off] = __float2bfloat16_rn(v - __bfloat162float(hb));
        } else {
            outp[off] = v;
        }
    }
}

// ---------------------------------------------------------------------------
// Launch
// ---------------------------------------------------------------------------
extern "C" void kernel_launch(void* const* d_in, const int* in_sizes, int n_in,
                              void* d_out, int out_size) {
    (void)in_sizes; (void)n_in; (void)out_size;
    const float* q  = (const float*)d_in[0];
    const float* Wq = (const float*)d_in[2];
    const float* bq = (const float*)d_in[3];
    const float* Wv = (const float*)d_in[4];
    const float* bv = (const float*)d_in[5];
    const float* Wo = (const float*)d_in[6];
    const float* bo = (const float*)d_in[7];
    const float* gm = (const float*)d_in[8];
    const float* lg = (const float*)d_in[9];
    const float* lb = (const float*)d_in[10];
    const float* fg = (const float*)d_in[11];
    const float* fb = (const float*)d_in[12];
    float* out = (float*)d_out;

    static int smem_set = 0;
    const int GEMM_SMEM = 2 * G_STG * 4;       // 75776 B
    const int SC_SMEM = 4 * 128 * 36 * 4;      // 73728 B
    if (!smem_set) {
        cudaFuncSetAttribute(gemm_bf16, cudaFuncAttributeMaxDynamicSharedMemorySize, GEMM_SMEM);
        cudaFuncSetAttribute(scores_bf16, cudaFuncAttributeMaxDynamicSharedMemorySize, SC_SMEM);
        smem_set = 1;
    }

    uint32_t *wqh, *wql, *wvh, *wvl, *woh, *wol;
    cudaGetSymbolAddress((void**)&wqh, g_wq_h); cudaGetSymbolAddress((void**)&wql, g_wq_l);
    cudaGetSymbolAddress((void**)&wvh, g_wv_h); cudaGetSymbolAddress((void**)&wvl, g_wv_l);
    cudaGetSymbolAddress((void**)&woh, g_wo_h); cudaGetSymbolAddress((void**)&wol, g_wo_l);
    __nv_bfloat16 *xh, *xl, *qph, *qpl, *aoh, *aol;
    cudaGetSymbolAddress((void**)&xh, g_xh);   cudaGetSymbolAddress((void**)&xl, g_xl);
    cudaGetSymbolAddress((void**)&qph, g_qph); cudaGetSymbolAddress((void**)&qpl, g_qpl);
    cudaGetSymbolAddress((void**)&aoh, g_aoh); cudaGetSymbolAddress((void**)&aol, g_aol);
    float *vhp, *yp;
    cudaGetSymbolAddress((void**)&vhp, g_vh);
    cudaGetSymbolAddress((void**)&yp, g_y);

    copy_in_split<<<(MR * DD) / 256, 256>>>(q);
    pack_w<<<WPK / 256, 256>>>(Wq, wqh, wql);
    pack_w<<<WPK / 256, 256>>>(Wv, wvh, wvl);
    pack_w<<<WPK / 256, 256>>>(Wo, woh, wol);

    const dim3 gg(8, 16);
    for (int l = 0; l < LL; l++) {
        size_t wo = (size_t)l * 512 * 1024;
        gemm_bf16<<<gg, 128, GEMM_SMEM>>>((const uint32_t*)xh, (const uint32_t*)xl,
                                          wqh + wo, wql + wo, bq + l * DD,
                                          1, nullptr, qph, qpl);
        gemm_bf16<<<gg, 128, GEMM_SMEM>>>((const uint32_t*)xh, (const uint32_t*)xl,
                                          wvh + wo, wvl + wo, bv + l * DD,
                                          0, vhp, nullptr, nullptr);
        scores_bf16<<<dim3(8, 8, BB * HH), 128, SC_SMEM>>>((const uint32_t*)qph,
                                                           (const uint32_t*)qpl);
        attn_kernel<<<dim3(SS, HH, BB), 256>>>(gm + l * HH);
        gemm_bf16<<<gg, 128, GEMM_SMEM>>>((const uint32_t*)aoh, (const uint32_t*)aol,
                                          woh + wo, wol + wo, bo + l * DD,
                                          0, yp, nullptr, nullptr);
        add_ln<<<MR, 256>>>(0, lg + l * DD, lb + l * DD, nullptr);
    }
    add_ln<<<MR, 256>>>(1, fg, fb, out);
}

// round 8
// speedup vs baseline: 2.7315x; 1.6762x over previous
#include <cuda_runtime.h>
#include <cuda_bf16.h>
#include <math.h>
#include <stdint.h>

#define BB 2
#define SS 1024
#define DD 1024
#define HH 16
#define LL 4
#define DHH 64
#define MR 2048  // B*S

// ---------------------------------------------------------------------------
// Scratch (device globals; no allocation)
// ---------------------------------------------------------------------------
__device__ float g_x [MR * DD];
__device__ float g_vh[MR * DD];
__device__ float g_y [MR * DD];
__device__ float g_sc[(size_t)BB * HH * SS * SS];  // scores, then coeff pairs in-place

__device__ __nv_bfloat16 g_xh [MR * DD], g_xl [MR * DD];
__device__ __nv_bfloat16 g_qph[MR * DD], g_qpl[MR * DD];
__device__ __nv_bfloat16 g_aoh[MR * DD], g_aol[MR * DD];

// V transposed + packed per (b,h): [bh][d][kp] u32 = (bf16 V[2kp][d], bf16 V[2kp+1][d])
__device__ uint32_t g_vth[BB * HH * DHH * 512], g_vtl[BB * HH * DHH * 512];

// packed weights: [l][kp][n] u32 = (bf16 W[2kp][n], bf16 W[2kp+1][n])
#define WPK (LL * 512 * DD)
__device__ uint32_t g_wq_h[WPK], g_wq_l[WPK];
__device__ uint32_t g_wv_h[WPK], g_wv_l[WPK];
__device__ uint32_t g_wo_h[WPK], g_wo_l[WPK];

// ---------------------------------------------------------------------------
__device__ __forceinline__ void mma16(float c[4], const uint32_t a[4], const uint32_t b[2]) {
    asm volatile(
        "mma.sync.aligned.m16n8k16.row.col.f32.bf16.bf16.f32 "
        "{%0,%1,%2,%3}, {%4,%5,%6,%7}, {%8,%9}, {%0,%1,%2,%3};\n"
        : "+f"(c[0]), "+f"(c[1]), "+f"(c[2]), "+f"(c[3])
        : "r"(a[0]), "r"(a[1]), "r"(a[2]), "r"(a[3]), "r"(b[0]), "r"(b[1]));
}
__device__ __forceinline__ void cp16(uint32_t saddr, const void* g) {
    asm volatile("cp.async.cg.shared.global [%0], [%1], 16;\n" :: "r"(saddr), "l"(g));
}
__device__ __forceinline__ uint16_t bfbits(__nv_bfloat16 b) { return *(uint16_t*)&b; }
__device__ __forceinline__ void split2(float v0, float v1, uint32_t& hi, uint32_t& lo) {
    __nv_bfloat16 h0 = __float2bfloat16_rn(v0), h1 = __float2bfloat16_rn(v1);
    __nv_bfloat16 l0 = __float2bfloat16_rn(v0 - __bfloat162float(h0));
    __nv_bfloat16 l1 = __float2bfloat16_rn(v1 - __bfloat162float(h1));
    hi = (uint32_t)bfbits(h0) | ((uint32_t)bfbits(h1) << 16);
    lo = (uint32_t)bfbits(l0) | ((uint32_t)bfbits(l1) << 16);
}
__device__ __forceinline__ float blkMax(float v, float* red) {
    int lane = threadIdx.x & 31, w = threadIdx.x >> 5;
#pragma unroll
    for (int o = 16; o; o >>= 1) v = fmaxf(v, __shfl_xor_sync(0xffffffffu, v, o));
    if (lane == 0) red[w] = v;
    __syncthreads();
    float r = red[0];
#pragma unroll
    for (int i = 1; i < 8; i++) r = fmaxf(r, red[i]);
    __syncthreads();
    return r;
}
__device__ __forceinline__ float blkSum(float v, float* red) {
    int lane = threadIdx.x & 31, w = threadIdx.x >> 5;
#pragma unroll
    for (int o = 16; o; o >>= 1) v += __shfl_xor_sync(0xffffffffu, v, o);
    if (lane == 0) red[w] = v;
    __syncthreads();
    float r = 0.f;
#pragma unroll
    for (int i = 0; i < 8; i++) r += red[i];
    __syncthreads();
    return r;
}

// ---------------------------------------------------------------------------
__global__ void copy_in_split(const float* __restrict__ src) {
    int i = blockIdx.x * blockDim.x + threadIdx.x;
    float x = src[i];
    g_x[i] = x;
    __nv_bfloat16 h = __float2bfloat16_rn(x);
    g_xh[i] = h;
    g_xl[i] = __float2bfloat16_rn(x - __bfloat162float(h));
}

__global__ void pack_w(const float* __restrict__ W, uint32_t* __restrict__ ph,
                       uint32_t* __restrict__ pl) {
    int idx = blockIdx.x * blockDim.x + threadIdx.x;
    int l = idx >> 19;
    int rem = idx & ((1 << 19) - 1);
    int kp = rem >> 10, n = rem & 1023;
    size_t base = (size_t)l * DD * DD;
    float f0 = W[base + (size_t)(2 * kp) * DD + n];
    float f1 = W[base + (size_t)(2 * kp + 1) * DD + n];
    uint32_t hi, lo;
    split2(f0, f1, hi, lo);
    ph[idx] = hi;
    pl[idx] = lo;
}

// ---------------------------------------------------------------------------
// V transpose-pack: g_vh fp32 [token][h*64+d] -> g_vth/l [bh][d][kp] u32 pairs
// ---------------------------------------------------------------------------
__global__ __launch_bounds__(256) void vt_pack() {
    const int tb = blockIdx.x, bh = blockIdx.y, b = bh >> 4, h = bh & 15;
    __shared__ float vs[64][65];
    const int tid = threadIdx.x;
#pragma unroll
    for (int j = 0; j < 16; j++) {
        int id = tid + j * 256;
        int t = id >> 6, d = id & 63;
        vs[t][d] = g_vh[(size_t)(b * SS + tb * 64 + t) * DD + h * 64 + d];
    }
    __syncthreads();
#pragma unroll
    for (int j = 0; j < 8; j++) {
        int id = tid + j * 256;
        int d = id >> 5, kp = id & 31;
        uint32_t hi, lo;
        split2(vs[2 * kp][d], vs[2 * kp + 1][d], hi, lo);
        size_t off = ((size_t)bh * 64 + d) * 512 + tb * 32 + kp;
        g_vth[off] = hi;
        g_vtl[off] = lo;
    }
}

// ---------------------------------------------------------------------------
// bf16 split GEMM: C[2048,1024] = A @ W + bias.  128x128 tile, BK=32 (16 u32),
// 128 threads (4 warps, 2x2 of 64x64), cp.async double-buffered.
// mode = blockIdx.z + zbase: 0 -> W0/bias0, split out (Oh/Ol); 1 -> W1/bias1, fp32 Cf.
// ---------------------------------------------------------------------------
#define G_AS  (128 * 20)
#define G_BS  (16 * 136)
#define G_STG (2 * G_AS + 2 * G_BS)

extern __shared__ uint32_t smdyn[];

__device__ __forceinline__ void gemm_issue(uint32_t sbase, int s, int kp0, int tid,
                                           int m0, int n0,
                                           const uint32_t* Ah, const uint32_t* Al,
                                           const uint32_t* Wh, const uint32_t* Wl) {
    uint32_t st = sbase + (uint32_t)(s * G_STG) * 4u;
#pragma unroll
    for (int i = 0; i < 4; i++) {
        int id = tid + i * 128;
        int m = id >> 2, kc = (id & 3) * 4;
        cp16(st + (uint32_t)(m * 20 + kc) * 4u, Ah + (size_t)(m0 + m) * 512 + kp0 + kc);
        cp16(st + (uint32_t)(G_AS + m * 20 + kc) * 4u, Al + (size_t)(m0 + m) * 512 + kp0 + kc);
    }
#pragma unroll
    for (int i = 0; i < 4; i++) {
        int id = tid + i * 128;
        int r = id >> 5, c = (id & 31) * 4;
        cp16(st + (uint32_t)(2 * G_AS + r * 136 + c) * 4u, Wh + (size_t)(kp0 + r) * 1024 + n0 + c);
        cp16(st + (uint32_t)(2 * G_AS + G_BS + r * 136 + c) * 4u, Wl + (size_t)(kp0 + r) * 1024 + n0 + c);
    }
    asm volatile("cp.async.commit_group;\n");
}

__global__ __launch_bounds__(128) void gemm_bf16(
    const uint32_t* __restrict__ Ah, const uint32_t* __restrict__ Al,
    const uint32_t* __restrict__ W0h, const uint32_t* __restrict__ W0l,
    const float* __restrict__ bias0,
    const uint32_t* __restrict__ W1h, const uint32_t* __restrict__ W1l,
    const float* __restrict__ bias1,
    int zbase, float* __restrict__ Cf,
    __nv_bfloat16* __restrict__ Oh, __nv_bfloat16* __restrict__ Ol) {
    const int mode = blockIdx.z + zbase;
    const uint32_t* Wh = (mode == 0) ? W0h : W1h;
    const uint32_t* Wl = (mode == 0) ? W0l : W1l;
    const float* bias = (mode == 0) ? bias0 : bias1;

    const int tid = threadIdx.x;
    const int m0 = blockIdx.y * 128, n0 = blockIdx.x * 128;
    const int wid = tid >> 5, lane = tid & 31;
    const int wm = wid >> 1, wn = wid & 1;
    const int gid = lane >> 2, tg = lane & 3;

    float acc[4][8][4];
#pragma unroll
    for (int i = 0; i < 4; i++)
#pragma unroll
        for (int j = 0; j < 8; j++)
#pragma unroll
            for (int k = 0; k < 4; k++) acc[i][j][k] = 0.f;

    const uint32_t sbase = (uint32_t)__cvta_generic_to_shared(smdyn);
    gemm_issue(sbase, 0, 0, tid, m0, n0, Ah, Al, Wh, Wl);

    for (int kt = 0; kt < 32; kt++) {
        if (kt < 31) {
            gemm_issue(sbase, (kt + 1) & 1, (kt + 1) * 16, tid, m0, n0, Ah, Al, Wh, Wl);
            asm volatile("cp.async.wait_group 1;\n");
        } else {
            asm volatile("cp.async.wait_group 0;\n");
        }
        __syncthreads();

        const uint32_t* pS = smdyn + (kt & 1) * G_STG;
        const uint32_t* pAh = pS;
        const uint32_t* pAl = pS + G_AS;
        const uint32_t* pBh = pS + 2 * G_AS;
        const uint32_t* pBl = pS + 2 * G_AS + G_BS;

#pragma unroll
        for (int kpb = 0; kpb < 16; kpb += 8) {
            uint32_t afh[4][4], afl[4][4];
#pragma unroll
            for (int mt = 0; mt < 4; mt++) {
                int r = wm * 64 + mt * 16 + gid;
                afh[mt][0] = pAh[r * 20 + kpb + tg];
                afh[mt][1] = pAh[(r + 8) * 20 + kpb + tg];
                afh[mt][2] = pAh[r * 20 + kpb + 4 + tg];
                afh[mt][3] = pAh[(r + 8) * 20 + kpb + 4 + tg];
                afl[mt][0] = pAl[r * 20 + kpb + tg];
                afl[mt][1] = pAl[(r + 8) * 20 + kpb + tg];
                afl[mt][2] = pAl[r * 20 + kpb + 4 + tg];
                afl[mt][3] = pAl[(r + 8) * 20 + kpb + 4 + tg];
            }
#pragma unroll
            for (int nt = 0; nt < 8; nt++) {
                int c = wn * 64 + nt * 8 + gid;
                uint32_t bfh[2], bfl[2];
                bfh[0] = pBh[(kpb + tg) * 136 + c];
                bfh[1] = pBh[(kpb + 4 + tg) * 136 + c];
                bfl[0] = pBl[(kpb + tg) * 136 + c];
                bfl[1] = pBl[(kpb + 4 + tg) * 136 + c];
#pragma unroll
                for (int mt = 0; mt < 4; mt++) {
                    mma16(acc[mt][nt], afh[mt], bfh);
                    mma16(acc[mt][nt], afh[mt], bfl);
                    mma16(acc[mt][nt], afl[mt], bfh);
                }
            }
        }
        __syncthreads();
    }

#pragma unroll
    for (int mt = 0; mt < 4; mt++) {
        int r = m0 + wm * 64 + mt * 16 + gid;
#pragma unroll
        for (int nt = 0; nt < 8; nt++) {
            int c = n0 + wn * 64 + nt * 8 + 2 * tg;
            float b0 = bias[c], b1 = bias[c + 1];
            float v0 = acc[mt][nt][0] + b0, v1 = acc[mt][nt][1] + b1;
            float v2 = acc[mt][nt][2] + b0, v3 = acc[mt][nt][3] + b1;
            if (mode != 0) {
                *(float2*)&Cf[(size_t)r * 1024 + c] = make_float2(v0, v1);
                *(float2*)&Cf[(size_t)(r + 8) * 1024 + c] = make_float2(v2, v3);
            } else {
                uint32_t hi, lo;
                split2(v0, v1, hi, lo);
                *(uint32_t*)&Oh[(size_t)r * 1024 + c] = hi;
                *(uint32_t*)&Ol[(size_t)r * 1024 + c] = lo;
                split2(v2, v3, hi, lo);
                *(uint32_t*)&Oh[(size_t)(r + 8) * 1024 + c] = hi;
                *(uint32_t*)&Ol[(size_t)(r + 8) * 1024 + c] = lo;
            }
        }
    }
}

// ---------------------------------------------------------------------------
// Scores via bf16 split: S = Qh @ Qh^T / 8 per (b,h). 128x128 tiles,
// lower-triangular only, dh=64 resident in smem.
// ---------------------------------------------------------------------------
__global__ __launch_bounds__(128) void scores_bf16(const uint32_t* __restrict__ Ph,
                                                   const uint32_t* __restrict__ Pl) {
    const int kt = blockIdx.x, qt = blockIdx.y;
    if (kt > qt) return;
    const int bh = blockIdx.z, b = bh >> 4, h = bh & 15;

    const int SZ = 128 * 36;
    uint32_t* sQh = smdyn;
    uint32_t* sQl = smdyn + SZ;
    uint32_t* sKh = smdyn + 2 * SZ;
    uint32_t* sKl = smdyn + 3 * SZ;

    const int tid = threadIdx.x;
#pragma unroll
    for (int i = 0; i < 8; i++) {
        int id = tid + i * 128;
        int m = id >> 3, c = (id & 7) * 4;
        size_t qoff = (size_t)(b * SS + qt * 128 + m) * 512 + h * 32 + c;
        size_t koff = (size_t)(b * SS + kt * 128 + m) * 512 + h * 32 + c;
        *(uint4*)&sQh[m * 36 + c] = *(const uint4*)(Ph + qoff);
        *(uint4*)&sQl[m * 36 + c] = *(const uint4*)(Pl + qoff);
        *(uint4*)&sKh[m * 36 + c] = *(const uint4*)(Ph + koff);
        *(uint4*)&sKl[m * 36 + c] = *(const uint4*)(Pl + koff);
    }
    __syncthreads();

    const int wid = tid >> 5, lane = tid & 31;
    const int wm = wid >> 1, wn = wid & 1;
    const int gid = lane >> 2, tg = lane & 3;

    float acc[4][8][4];
#pragma unroll
    for (int i = 0; i < 4; i++)
#pragma unroll
        for (int j = 0; j < 8; j++)
#pragma unroll
            for (int k = 0; k < 4; k++) acc[i][j][k] = 0.f;

#pragma unroll
    for (int kpb = 0; kpb < 32; kpb += 8) {
        uint32_t afh[4][4], afl[4][4];
#pragma unroll
        for (int mt = 0; mt < 4; mt++) {
            int r = wm * 64 + mt * 16 + gid;
            afh[mt][0] = sQh[r * 36 + kpb + tg];
            afh[mt][1] = sQh[(r + 8) * 36 + kpb + tg];
            afh[mt][2] = sQh[r * 36 + kpb + 4 + tg];
            afh[mt][3] = sQh[(r + 8) * 36 + kpb + 4 + tg];
            afl[mt][0] = sQl[r * 36 + kpb + tg];
            afl[mt][1] = sQl[(r + 8) * 36 + kpb + tg];
            afl[mt][2] = sQl[r * 36 + kpb + 4 + tg];
            afl[mt][3] = sQl[(r + 8) * 36 + kpb + 4 + tg];
        }
#pragma unroll
        for (int nt = 0; nt < 8; nt++) {
            int n = wn * 64 + nt * 8 + gid;
            uint32_t bfh[2], bfl[2];
            bfh[0] = sKh[n * 36 + kpb + tg];
            bfh[1] = sKh[n * 36 + kpb + 4 + tg];
            bfl[0] = sKl[n * 36 + kpb + tg];
            bfl[1] = sKl[n * 36 + kpb + 4 + tg];
#pragma unroll
            for (int mt = 0; mt < 4; mt++) {
                mma16(acc[mt][nt], afh[mt], bfh);
                mma16(acc[mt][nt], afh[mt], bfl);
                mma16(acc[mt][nt], afl[mt], bfh);
            }
        }
    }

#pragma unroll
    for (int mt = 0; mt < 4; mt++) {
        int row = qt * 128 + wm * 64 + mt * 16 + gid;
#pragma unroll
        for (int nt = 0; nt < 8; nt++) {
            int col = kt * 128 + wn * 64 + nt * 8 + 2 * tg;
            size_t off = ((size_t)bh * SS + row) * SS + col;
            *(float2*)&g_sc[off] =
                make_float2(acc[mt][nt][0] * 0.125f, acc[mt][nt][1] * 0.125f);
            *(float2*)&g_sc[off + 8 * SS] =
                make_float2(acc[mt][nt][2] * 0.125f, acc[mt][nt][3] * 0.125f);
        }
    }
}

// ---------------------------------------------------------------------------
// Attention softmax kernel: per (b,h,q). Writes packed bf16 hi/lo coefficient
// pairs IN-PLACE into the g_sc row: hi pairs at u32[0..511], lo at u32[512..1023].
// ---------------------------------------------------------------------------
__global__ __launch_bounds__(256) void attn_kernel(const float* __restrict__ gam) {
    const int q = blockIdx.x, h = blockIdx.y, b = blockIdx.z;
    const int bh = b * HH + h;
    const int tid = threadIdx.x, lane = tid & 31, w = tid >> 5;

    uint32_t* scu = (uint32_t*)g_sc;
    const size_t rb = ((size_t)bh * SS + q) * SS;
    const int nv = q;
    if (nv == 0) {
        scu[rb + tid] = 0u;
        scu[rb + 256 + tid] = 0u;
        scu[rb + 512 + tid] = 0u;
        scu[rb + 768 + tid] = 0u;
        return;
    }

    __shared__ float red[8];

    const float* srow = g_sc + rb;
    const float gneg = -fabsf(gam[h]);
    const int k0 = tid * 4;

    float sv[4];
    bool val[4];
    float m1 = -3.0e38f;
#pragma unroll
    for (int i = 0; i < 4; i++) {
        int k = k0 + i;
        val[i] = (k < nv);
        sv[i] = val[i] ? srow[k] : 0.f;
        if (val[i]) m1 = fmaxf(m1, sv[i]);
    }
    m1 = blkMax(m1, red);

    float e[4];
#pragma unroll
    for (int i = 0; i < 4; i++) e[i] = val[i] ? __expf(sv[i] - m1) : 0.f;

    float l0 = e[0], l1 = l0 + e[1], l2 = l1 + e[2], l3 = l2 + e[3];
    float tot = l3, xs = tot;
#pragma unroll
    for (int o = 1; o < 32; o <<= 1) {
        float y = __shfl_up_sync(0xffffffffu, xs, o);
        if (lane >= o) xs += y;
    }
    if (lane == 31) red[w] = xs;
    __syncthreads();
    float woff = 0.f, sum1 = 0.f;
#pragma unroll
    for (int i = 0; i < 8; i++) {
        float t = red[i];
        sum1 += t;
        if (i < w) woff += t;
    }
    __syncthreads();
    const float exc = woff + xs - tot;
    float cum[4] = {exc + l0, exc + l1, exc + l2, exc + l3};

    const float rs = __fdividef(1.f, sum1);
    float s2[4];
    float m2 = -3.0e38f;
#pragma unroll
    for (int i = 0; i < 4; i++) {
        if (val[i]) {
            float frac = fmaxf((sum1 - cum[i]) * rs, 0.f);
            float dist = sqrtf(frac * (float)(q - (k0 + i)));
            float eff = __expf(dist * gneg);
            eff = fminf(fmaxf(eff, 1e-5f), 1e5f);
            s2[i] = sv[i] * eff;
            m2 = fmaxf(m2, s2[i]);
        } else {
            s2[i] = 0.f;
        }
    }
    m2 = blkMax(m2, red);

    float a[4], lsum = 0.f;
#pragma unroll
    for (int i = 0; i < 4; i++) {
        a[i] = val[i] ? __expf(s2[i] - m2) : 0.f;
        lsum += a[i];
    }
    float sum2 = blkSum(lsum, red);
    // max attn weight = exp(0)/sum2 -> scale = min(sum2, 5)
    const float coef = __fdividef(fminf(sum2, 5.f), sum2);

    uint32_t h0, lo0, h1, lo1;
    split2(a[0] * coef, a[1] * coef, h0, lo0);
    split2(a[2] * coef, a[3] * coef, h1, lo1);
    scu[rb + 2 * tid] = h0;
    scu[rb + 2 * tid + 1] = h1;
    scu[rb + 512 + 2 * tid] = lo0;
    scu[rb + 512 + 2 * tid + 1] = lo1;
}

// ---------------------------------------------------------------------------
// PV GEMM: O[128 q, 64 d] = C @ V per (qt, bh). 3-term bf16 mma,
// cp.async double-buffered, causal K bound. Writes aoh/aol split directly.
// smem (u32): per stage: A_h 128*20, A_l 128*20, V_h 64*20, V_l 64*20 = 7680
// ---------------------------------------------------------------------------
#define PV_STG 7680
#define PV_AL  2560
#define PV_VH  5120
#define PV_VL  6400

__device__ __forceinline__ void pv_issue(uint32_t sbase, int st, int ck0, int tid,
                                         int bh, int qt, const uint32_t* scu,
                                         const uint32_t* vth, const uint32_t* vtl) {
    uint32_t sb = sbase + (uint32_t)(st * PV_STG) * 4u;
#pragma unroll
    for (int j = 0; j < 2; j++) {
        int id = tid + j * 256;
        int r = id >> 2, kc = (id & 3) * 4;
        size_t src = ((size_t)bh * SS + qt * 128 + r) * SS + ck0 + kc;
        cp16(sb + (uint32_t)(r * 20 + kc) * 4u, scu + src);
        cp16(sb + (uint32_t)(PV_AL + r * 20 + kc) * 4u, scu + src + 512);
    }
    {
        int d = tid >> 2, kc = (tid & 3) * 4;
        size_t vs = ((size_t)bh * 64 + d) * 512 + ck0 + kc;
        cp16(sb + (uint32_t)(PV_VH + d * 20 + kc) * 4u, vth + vs);
        cp16(sb + (uint32_t)(PV_VL + d * 20 + kc) * 4u, vtl + vs);
    }
    asm volatile("cp.async.commit_group;\n");
}

__global__ __launch_bounds__(256) void pv_gemm(const uint32_t* __restrict__ scu,
                                               const uint32_t* __restrict__ vth,
                                               const uint32_t* __restrict__ vtl,
                                               __nv_bfloat16* __restrict__ Oh,
                                               __nv_bfloat16* __restrict__ Ol) {
    const int qt = blockIdx.x, bh = blockIdx.y, b = bh >> 4, h = bh & 15;
    const int tid = threadIdx.x, w = tid >> 5, lane = tid & 31;
    const int gid = lane >> 2, tg = lane & 3;

    float acc[8][4];
#pragma unroll
    for (int j = 0; j < 8; j++)
#pragma unroll
        for (int k = 0; k < 4; k++) acc[j][k] = 0.f;

    const int nch = (qt + 1) * 4;  // chunks of 16 kp (32 tokens)
    const uint32_t sbase = (uint32_t)__cvta_generic_to_shared(smdyn);

    pv_issue(sbase, 0, 0, tid, bh, qt, scu, vth, vtl);

    for (int c = 0; c < nch; c++) {
        if (c + 1 < nch) {
            pv_issue(sbase, (c + 1) & 1, (c + 1) * 16, tid, bh, qt, scu, vth, vtl);
            asm volatile("cp.async.wait_group 1;\n");
        } else {
            asm volatile("cp.async.wait_group 0;\n");
        }
        __syncthreads();

        const uint32_t* pS = smdyn + (c & 1) * PV_STG;
        const uint32_t* pAh = pS;
        const uint32_t* pAl = pS + PV_AL;
        const uint32_t* pVh = pS + PV_VH;
        const uint32_t* pVl = pS + PV_VL;

#pragma unroll
        for (int s = 0; s < 2; s++) {
            uint32_t ah[4], al[4];
            int r = w * 16 + gid;
            ah[0] = pAh[r * 20 + s * 8 + tg];
            ah[1] = pAh[(r + 8) * 20 + s * 8 + tg];
            ah[2] = pAh[r * 20 + s * 8 + 4 + tg];
            ah[3] = pAh[(r + 8) * 20 + s * 8 + 4 + tg];
            al[0] = pAl[r * 20 + s * 8 + tg];
            al[1] = pAl[(r + 8) * 20 + s * 8 + tg];
            al[2] = pAl[r * 20 + s * 8 + 4 + tg];
            al[3] = pAl[(r + 8) * 20 + s * 8 + 4 + tg];
#pragma unroll
            for (int nt = 0; nt < 8; nt++) {
                int base = (nt * 8 + gid) * 20 + s * 8;
                uint32_t bh2[2], bl2[2];
                bh2[0] = pVh[base + tg];
                bh2[1] = pVh[base + 4 + tg];
                bl2[0] = pVl[base + tg];
                bl2[1] = pVl[base + 4 + tg];
                mma16(acc[nt], ah, bh2);
                mma16(acc[nt], ah, bl2);
                mma16(acc[nt], al, bh2);
            }
        }
        __syncthreads();
    }

    const int qrow = qt * 128 + w * 16 + gid;
#pragma unroll
    for (int nt = 0; nt < 8; nt++) {
        int col = h * 64 + nt * 8 + 2 * tg;
        size_t o0 = (size_t)(b * SS + qrow) * DD + col;
        size_t o1 = (size_t)(b * SS + qrow + 8) * DD + col;
        uint32_t hi, lo;
        split2(acc[nt][0], acc[nt][1], hi, lo);
        *(uint32_t*)&Oh[o0] = hi;
        *(uint32_t*)&Ol[o0] = lo;
        split2(acc[nt][2], acc[nt][3], hi, lo);
        *(uint32_t*)&Oh[o1] = hi;
        *(uint32_t*)&Ol[o1] = lo;
    }
}

// ---------------------------------------------------------------------------
// Residual + LayerNorm. mode 0: g_x = LN(g_x + g_y) + bf16 split. mode 1: final.
// ---------------------------------------------------------------------------
__global__ __launch_bounds__(256) void add_ln(int mode,
                                              const float* __restrict__ gam,
                                              const float* __restrict__ beta,
                                              float* __restrict__ outp) {
    const int row = blockIdx.x;
    __shared__ float t[1024];
    __shared__ float red[8];
    const float* xr = g_x + (size_t)row * 1024;
    const float* yr = g_y + (size_t)row * 1024;
    const int tid = threadIdx.x;

    float lsum = 0.f;
#pragma unroll
    for (int i = 0; i < 4; i++) {
        int d = tid + i * 256;
        float v = xr[d] + (mode == 0 ? yr[d] : 0.f);
        t[d] = v;
        lsum += v;
    }
    float mu = blkSum(lsum, red) * (1.f / 1024.f);

    float lsq = 0.f;
#pragma unroll
    for (int i = 0; i < 4; i++) {
        int d = tid + i * 256;
        float dv = t[d] - mu;
        lsq += dv * dv;
    }
    float var = blkSum(lsq, red) * (1.f / 1024.f);
    float rinv = rsqrtf(var + 1e-5f);

#pragma unroll
    for (int i = 0; i < 4; i++) {
        int d = tid + i * 256;
        float v = (t[d] - mu) * rinv * gam[d] + beta[d];
        size_t off = (size_t)row * 1024 + d;
        if (mode == 0) {
            g_x[off] = v;
            __nv_bfloat16 hb = __float2bfloat16_rn(v);
            g_xh[off] = hb;
            g_xl[off] = __float2bfloat16_rn(v - __bfloat162float(hb));
        } else {
            outp[off] = v;
        }
    }
}

// ---------------------------------------------------------------------------
// Launch
// ---------------------------------------------------------------------------
extern "C" void kernel_launch(void* const* d_in, const int* in_sizes, int n_in,
                              void* d_out, int out_size) {
    (void)in_sizes; (void)n_in; (void)out_size;
    const float* q  = (const float*)d_in[0];
    const float* Wq = (const float*)d_in[2];
    const float* bq = (const float*)d_in[3];
    const float* Wv = (const float*)d_in[4];
    const float* bv = (const float*)d_in[5];
    const float* Wo = (const float*)d_in[6];
    const float* bo = (const float*)d_in[7];
    const float* gm = (const float*)d_in[8];
    const float* lg = (const float*)d_in[9];
    const float* lb = (const float*)d_in[10];
    const float* fg = (const float*)d_in[11];
    const float* fb = (const float*)d_in[12];
    float* out = (float*)d_out;

    const int GEMM_SMEM = 2 * G_STG * 4;       // 75776 B
    const int SC_SMEM = 4 * 128 * 36 * 4;      // 73728 B
    const int PV_SMEM = 2 * PV_STG * 4;        // 61440 B
    cudaFuncSetAttribute(gemm_bf16, cudaFuncAttributeMaxDynamicSharedMemorySize, GEMM_SMEM);
    cudaFuncSetAttribute(scores_bf16, cudaFuncAttributeMaxDynamicSharedMemorySize, SC_SMEM);
    cudaFuncSetAttribute(pv_gemm, cudaFuncAttributeMaxDynamicSharedMemorySize, PV_SMEM);

    uint32_t *wqh, *wql, *wvh, *wvl, *woh, *wol, *vth, *vtl, *scu;
    cudaGetSymbolAddress((void**)&wqh, g_wq_h); cudaGetSymbolAddress((void**)&wql, g_wq_l);
    cudaGetSymbolAddress((void**)&wvh, g_wv_h); cudaGetSymbolAddress((void**)&wvl, g_wv_l);
    cudaGetSymbolAddress((void**)&woh, g_wo_h); cudaGetSymbolAddress((void**)&wol, g_wo_l);
    cudaGetSymbolAddress((void**)&vth, g_vth);  cudaGetSymbolAddress((void**)&vtl, g_vtl);
    cudaGetSymbolAddress((void**)&scu, g_sc);
    __nv_bfloat16 *xh, *xl, *qph, *qpl, *aoh, *aol;
    cudaGetSymbolAddress((void**)&xh, g_xh);   cudaGetSymbolAddress((void**)&xl, g_xl);
    cudaGetSymbolAddress((void**)&qph, g_qph); cudaGetSymbolAddress((void**)&qpl, g_qpl);
    cudaGetSymbolAddress((void**)&aoh, g_aoh); cudaGetSymbolAddress((void**)&aol, g_aol);
    float *vhp, *yp;
    cudaGetSymbolAddress((void**)&vhp, g_vh);
    cudaGetSymbolAddress((void**)&yp, g_y);

    copy_in_split<<<(MR * DD) / 256, 256>>>(q);
    pack_w<<<WPK / 256, 256>>>(Wq, wqh, wql);
    pack_w<<<WPK / 256, 256>>>(Wv, wvh, wvl);
    pack_w<<<WPK / 256, 256>>>(Wo, woh, wol);

    for (int l = 0; l < LL; l++) {
        size_t wo = (size_t)l * 512 * 1024;
        // fused Q + V projections (z=0: Q -> split, z=1: V -> fp32)
        gemm_bf16<<<dim3(8, 16, 2), 128, GEMM_SMEM>>>(
            (const uint32_t*)xh, (const uint32_t*)xl,
            wqh + wo, wql + wo, bq + l * DD,
            wvh + wo, wvl + wo, bv + l * DD,
            0, vhp, qph, qpl);
        vt_pack<<<dim3(16, BB * HH), 256>>>();
        scores_bf16<<<dim3(8, 8, BB * HH), 128, SC_SMEM>>>((const uint32_t*)qph,
                                                           (const uint32_t*)qpl);
        attn_kernel<<<dim3(SS, HH, BB), 256>>>(gm + l * HH);
        pv_gemm<<<dim3(8, BB * HH), 256, PV_SMEM>>>(scu, vth, vtl, aoh, aol);
        // output projection (mode 1 via zbase: fp32 out)
        gemm_bf16<<<dim3(8, 16, 1), 128, GEMM_SMEM>>>(
            (const uint32_t*)aoh, (const uint32_t*)aol,
            nullptr, nullptr, nullptr,
            woh + wo, wol + wo, bo + l * DD,
            1, yp, nullptr, nullptr);
        add_ln<<<MR, 256>>>(0, lg + l * DD, lb + l * DD, nullptr);
    }
    add_ln<<<MR, 256>>>(1, fg, fb, out);
}